// round 1
// baseline (speedup 1.0000x reference)
#include <cuda_runtime.h>
#include <cuda_fp16.h>
#include <cstdint>

#define HH 96
#define WW 96
#define HWPIX 9216
#define CTOT 2880
#define NBOX 512

// Static device scratch (no allocations allowed).
__device__ __half g_B[HWPIX * CTOT];    // fused feature map, [pixel][channel], fp16
__device__ __half g_A[NBOX * HWPIX];    // ROI weight matrix, [box][pixel], fp16
__device__ float  g_T[2304*384 + 576*768 + 144*1536];  // transposed levels 1..3: [hw][C]

// ---------------- level0: transpose [192][9216] fp32 -> g_B[:, 0:192] fp16 ----------------
__global__ void k_trans0(const float* __restrict__ src) {
    __shared__ float tile[32][33];
    int p0 = blockIdx.x * 32, c0 = blockIdx.y * 32;
    int tx = threadIdx.x, ty = threadIdx.y;
    #pragma unroll
    for (int i = 0; i < 32; i += 8)
        tile[ty + i][tx] = src[(size_t)(c0 + ty + i) * HWPIX + p0 + tx];
    __syncthreads();
    #pragma unroll
    for (int i = 0; i < 32; i += 8)
        g_B[(size_t)(p0 + ty + i) * CTOT + c0 + tx] = __float2half(tile[tx][ty + i]);
}

// ---------------- generic transpose: src[rows][cols] -> g_T[toff + c*rows + r] ----------------
__global__ void k_trans_f32(const float* __restrict__ src, int toff, int rows, int cols) {
    __shared__ float tile[32][33];
    int c0 = blockIdx.x * 32, r0 = blockIdx.y * 32;
    int tx = threadIdx.x, ty = threadIdx.y;
    #pragma unroll
    for (int i = 0; i < 32; i += 8) {
        int r = r0 + ty + i, c = c0 + tx;
        if (r < rows && c < cols) tile[ty + i][tx] = src[(size_t)r * cols + c];
    }
    __syncthreads();
    #pragma unroll
    for (int i = 0; i < 32; i += 8) {
        int c = c0 + ty + i, r = r0 + tx;
        if (c < cols && r < rows) g_T[toff + (size_t)c * rows + r] = tile[tx][ty + i];
    }
}

// ---------------- bilinear (half-pixel) upsample of one level into g_B columns ----------------
// One block per output pixel; threads sweep channels (coalesced reads of T[src_pix][c] and
// coalesced fp16 writes). Matches jax.image.resize('bilinear') == F.interpolate(align_corners=False).
__global__ void k_upsample(int toff, int Cl, int hsrc, float inv, int coff) {
    int p = blockIdx.x;
    int y = p / WW, x = p % WW;
    float Xf = fminf(fmaxf((x + 0.5f) * inv - 0.5f, 0.f), (float)hsrc - 1.f);
    float Yf = fminf(fmaxf((y + 0.5f) * inv - 0.5f, 0.f), (float)hsrc - 1.f);
    int x0 = min((int)Xf, hsrc - 2);
    int y0 = min((int)Yf, hsrc - 2);
    float fx = Xf - (float)x0, fy = Yf - (float)y0;
    const float* base = g_T + toff;
    const float* r00 = base + (size_t)(y0 * hsrc + x0) * Cl;
    const float* r01 = r00 + Cl;
    const float* r10 = r00 + (size_t)hsrc * Cl;
    const float* r11 = r10 + Cl;
    float w00 = (1.f-fy)*(1.f-fx), w01 = (1.f-fy)*fx, w10 = fy*(1.f-fx), w11 = fy*fx;
    __half* dst = g_B + (size_t)p * CTOT + coff;
    for (int c = threadIdx.x; c < Cl; c += blockDim.x) {
        float v = w00*r00[c] + w01*r01[c] + w10*r10[c] + w11*r11[c];
        dst[c] = __float2half(v);
    }
}

// ---------------- per-box separable ROI-align weights: W[y,x] = norm * Ay[y] * Ax[x] ----------------
__global__ void k_weights(const float* __restrict__ boxes) {
    __shared__ float Ax[96], Ay[96];
    __shared__ float s_norm;
    int k = blockIdx.x;
    int t = threadIdx.x;  // 128 threads
    if (t < 96) { Ax[t] = 0.f; Ay[t] = 0.f; }
    float x1 = boxes[k*4+0], y1 = boxes[k*4+1];
    float x2 = boxes[k*4+2], y2 = boxes[k*4+3];
    float rw = fmaxf(x2 - x1, 1.0f), rh = fmaxf(y2 - y1, 1.0f);
    float gw = fminf(fmaxf(ceilf(rw / 7.0f), 1.0f), 8.0f);
    float gh = fminf(fmaxf(ceilf(rh / 7.0f), 1.0f), 8.0f);
    if (t == 0) s_norm = 1.0f / (gh * gw * 49.0f);
    __syncthreads();
    if (t < 112) {
        int isY = t >= 56;
        int i = isY ? t - 56 : t;
        int pp = i >> 3, ss = i & 7;
        float lo = isY ? y1 : x1;
        float sz = isY ? rh : rw;
        float g  = isY ? gh : gw;
        float* Aarr = isY ? Ay : Ax;
        if ((float)ss < g) {
            float b = sz / 7.0f;
            float coord = lo + (float)pp * b + ((float)ss + 0.5f) * (b / g);
            if (!(coord < -1.0f || coord > 96.0f)) {   // torchvision: whole sample -> 0
                float c = fmaxf(coord, 0.0f);
                int i0 = (int)floorf(c);
                int i1; float f;
                if (i0 >= 95) { i0 = 95; i1 = 95; f = 0.f; }
                else          { i1 = i0 + 1; f = c - (float)i0; }
                atomicAdd(&Aarr[i0], 1.0f - f);
                atomicAdd(&Aarr[i1], f);
            }
        }
    }
    __syncthreads();
    float norm = s_norm;
    __half* row = g_A + (size_t)k * HWPIX;
    for (int i = t; i < HWPIX; i += 128) {
        int y = i / 96, x = i - y * 96;
        row[i] = __float2half(norm * Ay[y] * Ax[x]);
    }
}

// ---------------- fp16 GEMM: out[512,2880] = A[512,9216] @ B[9216,2880], fp32 accum ----------------
#define BM 64
#define BN 96
#define BK 64
#define BNP 104                  // padded B smem row (halfs) -> conflict-free ldmatrix.trans
#define KITERS (HWPIX / BK)      // 144

__device__ __forceinline__ void cp16(uint32_t d, const void* s) {
    asm volatile("cp.async.cg.shared.global [%0], [%1], 16;\n" :: "r"(d), "l"(s));
}
__device__ __forceinline__ void ldmatrix_x4(uint32_t &r0, uint32_t &r1, uint32_t &r2, uint32_t &r3, uint32_t addr) {
    asm volatile("ldmatrix.sync.aligned.m8n8.x4.shared.b16 {%0,%1,%2,%3}, [%4];\n"
                 : "=r"(r0),"=r"(r1),"=r"(r2),"=r"(r3) : "r"(addr));
}
__device__ __forceinline__ void ldmatrix_x2t(uint32_t &r0, uint32_t &r1, uint32_t addr) {
    asm volatile("ldmatrix.sync.aligned.m8n8.x2.trans.shared.b16 {%0,%1}, [%2];\n"
                 : "=r"(r0),"=r"(r1) : "r"(addr));
}
__device__ __forceinline__ void mma16816(float* d, const uint32_t* a, const uint32_t* b) {
    asm volatile("mma.sync.aligned.m16n8k16.row.col.f32.f16.f16.f32 "
                 "{%0,%1,%2,%3}, {%4,%5,%6,%7}, {%8,%9}, {%0,%1,%2,%3};\n"
                 : "+f"(d[0]),"+f"(d[1]),"+f"(d[2]),"+f"(d[3])
                 : "r"(a[0]),"r"(a[1]),"r"(a[2]),"r"(a[3]),"r"(b[0]),"r"(b[1]));
}

__global__ __launch_bounds__(256) void k_gemm(float* __restrict__ out) {
    __shared__ __align__(16) __half As[2][BM][BK];
    __shared__ __align__(16) __half Bs[2][BK][BNP];
    const int tid  = threadIdx.x;
    const int lane = tid & 31;
    const int warp = tid >> 5;           // 8 warps: 2 (M) x 4 (N)
    const int wm = (warp >> 2) * 32;     // warp tile 32 x 24
    const int wn = (warp & 3) * 24;
    const int bm0 = blockIdx.y * BM;
    const int bn0 = blockIdx.x * BN;

    const uint32_t asBase = (uint32_t)__cvta_generic_to_shared(&As[0][0][0]);
    const uint32_t bsBase = (uint32_t)__cvta_generic_to_shared(&Bs[0][0][0]);

    float acc[2][3][4];
    #pragma unroll
    for (int a = 0; a < 2; a++)
        #pragma unroll
        for (int b = 0; b < 3; b++)
            #pragma unroll
            for (int c = 0; c < 4; c++) acc[a][b][c] = 0.f;

    auto load_stage = [&](int stage, int k0) {
        uint32_t aS = asBase + stage * (BM*BK*2);
        uint32_t bS = bsBase + stage * (BK*BNP*2);
        int chunk = tid & 7, row = tid >> 3;
        #pragma unroll
        for (int r = row; r < BM; r += 32) {
            int sw = chunk ^ (r & 7);     // XOR swizzle, 16B granules
            cp16(aS + (r*8 + sw)*16, &g_A[(size_t)(bm0 + r) * HWPIX + k0 + chunk*8]);
        }
        #pragma unroll
        for (int idx = tid; idx < BK*12; idx += 256) {
            int r = idx / 12, cc = idx % 12;
            cp16(bS + (r*BNP + cc*8)*2, &g_B[(size_t)(k0 + r) * CTOT + bn0 + cc*8]);
        }
    };

    load_stage(0, 0);
    asm volatile("cp.async.commit_group;\n" ::: "memory");

    for (int kt = 0; kt < KITERS; kt++) {
        if (kt + 1 < KITERS) {
            load_stage((kt + 1) & 1, (kt + 1) * BK);
            asm volatile("cp.async.commit_group;\n" ::: "memory");
            asm volatile("cp.async.wait_group 1;\n" ::: "memory");
        } else {
            asm volatile("cp.async.wait_group 0;\n" ::: "memory");
        }
        __syncthreads();
        const int st = kt & 1;
        const uint32_t aS = asBase + st * (BM*BK*2);
        const uint32_t bS = bsBase + st * (BK*BNP*2);
        #pragma unroll
        for (int ks = 0; ks < 4; ks++) {
            uint32_t a[2][4];
            #pragma unroll
            for (int mt = 0; mt < 2; mt++) {
                int r  = wm + mt*16 + (lane & 15);
                int kc = ks*2 + (lane >> 4);
                ldmatrix_x4(a[mt][0], a[mt][1], a[mt][2], a[mt][3],
                            aS + (r*8 + (kc ^ (r & 7)))*16);
            }
            uint32_t b[3][2];
            #pragma unroll
            for (int nt = 0; nt < 3; nt++) {
                int r = ks*16 + (lane & 15);
                ldmatrix_x2t(b[nt][0], b[nt][1], bS + (r*BNP + wn + nt*8)*2);
            }
            #pragma unroll
            for (int mt = 0; mt < 2; mt++)
                #pragma unroll
                for (int nt = 0; nt < 3; nt++)
                    mma16816(acc[mt][nt], a[mt], b[nt]);
        }
        __syncthreads();
    }

    // Epilogue: direct fp32 stores (all tiles exact, no bounds checks needed).
    int r0 = lane >> 2, c0 = (lane & 3) * 2;
    #pragma unroll
    for (int mt = 0; mt < 2; mt++) {
        #pragma unroll
        for (int nt = 0; nt < 3; nt++) {
            int m = bm0 + wm + mt*16 + r0;
            int n = bn0 + wn + nt*8 + c0;
            *(float2*)&out[(size_t)m       * CTOT + n] = make_float2(acc[mt][nt][0], acc[mt][nt][1]);
            *(float2*)&out[(size_t)(m + 8) * CTOT + n] = make_float2(acc[mt][nt][2], acc[mt][nt][3]);
        }
    }
}

extern "C" void kernel_launch(void* const* d_in, const int* in_sizes, int n_in,
                              void* d_out, int out_size) {
    const float* feat0 = (const float*)d_in[0];
    const float* feat1 = (const float*)d_in[1];
    const float* feat2 = (const float*)d_in[2];
    const float* feat3 = (const float*)d_in[3];
    const float* boxes = (const float*)d_in[4];
    float* out = (float*)d_out;

    dim3 tb(32, 8);
    // Level 0: direct transpose into B columns [0,192)
    k_trans0<<<dim3(HWPIX/32, 192/32), tb>>>(feat0);
    // Levels 1..3: transpose to [hw][C] scratch
    k_trans_f32<<<dim3(2304/32, 384/32), tb>>>(feat1, 0,       384,  2304);
    k_trans_f32<<<dim3(576/32,  768/32), tb>>>(feat2, 884736,  768,  576);
    k_trans_f32<<<dim3(5,      1536/32), tb>>>(feat3, 1327104, 1536, 144);
    // Upsample into B columns
    k_upsample<<<HWPIX, 256>>>(0,       384,  48, 0.5f,   192);
    k_upsample<<<HWPIX, 256>>>(884736,  768,  24, 0.25f,  576);
    k_upsample<<<HWPIX, 256>>>(1327104, 1536, 12, 0.125f, 1344);
    // ROI weight rows
    k_weights<<<NBOX, 128>>>(boxes);
    // Pooling as dense fp16 GEMM
    k_gemm<<<dim3(CTOT/BN, NBOX/BM), 256>>>(out);
}

// round 3
// speedup vs baseline: 1.2503x; 1.2503x over previous
#include <cuda_runtime.h>
#include <cuda_fp16.h>
#include <cstdint>

#define HWPIX 9216
#define CTOT 2880
#define NBOX 512

// Static device scratch. Both operands K-major (K = pixel index).
__device__ __align__(256) __half g_B[(size_t)CTOT * HWPIX];   // [channel][pixel], 53MB
__device__ __align__(256) __half g_A[(size_t)NBOX * HWPIX];   // [box][pixel], 9.4MB

// ---------------- level0: fp32 -> fp16 elementwise into rows [0,192) ----------------
__global__ void k_conv0(const float4* __restrict__ src) {
    int i = blockIdx.x * 256 + threadIdx.x;   // grid sized exactly: 192*9216/4 float4s
    float4 v = src[i];
    __half2* d = reinterpret_cast<__half2*>(g_B);
    d[2 * i]     = __floats2half2_rn(v.x, v.y);
    d[2 * i + 1] = __floats2half2_rn(v.z, v.w);
}

// ---------------- bilinear half-pixel upsample, channel-major ----------------
// One block per channel; source plane (<=9KB) cached in smem; coalesced half stores.
__global__ void k_up(const float* __restrict__ src, int coff, int hsrc, float inv) {
    __shared__ float s[48 * 48];
    int c = blockIdx.x;
    const float* sc = src + (size_t)c * hsrc * hsrc;
    for (int i = threadIdx.x; i < hsrc * hsrc; i += 256) s[i] = sc[i];
    __syncthreads();
    __half* dst = g_B + (size_t)(coff + c) * HWPIX;
    for (int p = threadIdx.x; p < HWPIX; p += 256) {
        int y = p / 96, x = p - y * 96;
        float Xf = fminf(fmaxf(((float)x + 0.5f) * inv - 0.5f, 0.f), (float)(hsrc - 1));
        float Yf = fminf(fmaxf(((float)y + 0.5f) * inv - 0.5f, 0.f), (float)(hsrc - 1));
        int x0 = min((int)Xf, hsrc - 2);
        int y0 = min((int)Yf, hsrc - 2);
        float fx = Xf - (float)x0, fy = Yf - (float)y0;
        const float* r0 = s + y0 * hsrc + x0;
        float w00 = (1.f - fy) * (1.f - fx), w01 = (1.f - fy) * fx;
        float w10 = fy * (1.f - fx),         w11 = fy * fx;
        float v = w00 * r0[0] + w01 * r0[1] + w10 * r0[hsrc] + w11 * r0[hsrc + 1];
        dst[p] = __float2half(v);
    }
}

// ---------------- per-box separable ROI-align weights: W[y,x] = norm * Ay[y] * Ax[x] ----------------
__global__ void k_weights(const float* __restrict__ boxes) {
    __shared__ float Ax[96], Ay[96];
    __shared__ float s_norm;
    int k = blockIdx.x;
    int t = threadIdx.x;  // 128 threads
    if (t < 96) { Ax[t] = 0.f; Ay[t] = 0.f; }
    float x1 = boxes[k*4+0], y1 = boxes[k*4+1];
    float x2 = boxes[k*4+2], y2 = boxes[k*4+3];
    float rw = fmaxf(x2 - x1, 1.0f), rh = fmaxf(y2 - y1, 1.0f);
    float gw = fminf(fmaxf(ceilf(rw / 7.0f), 1.0f), 8.0f);
    float gh = fminf(fmaxf(ceilf(rh / 7.0f), 1.0f), 8.0f);
    if (t == 0) s_norm = 1.0f / (gh * gw * 49.0f);
    __syncthreads();
    if (t < 112) {
        int isY = t >= 56;
        int i = isY ? t - 56 : t;
        int pp = i >> 3, ss = i & 7;
        float lo = isY ? y1 : x1;
        float sz = isY ? rh : rw;
        float g  = isY ? gh : gw;
        float* Aarr = isY ? Ay : Ax;
        if ((float)ss < g) {
            float b = sz / 7.0f;
            float coord = lo + (float)pp * b + ((float)ss + 0.5f) * (b / g);
            if (!(coord < -1.0f || coord > 96.0f)) {
                float c = fmaxf(coord, 0.0f);
                int i0 = (int)floorf(c);
                int i1; float f;
                if (i0 >= 95) { i0 = 95; i1 = 95; f = 0.f; }
                else          { i1 = i0 + 1; f = c - (float)i0; }
                atomicAdd(&Aarr[i0], 1.0f - f);
                atomicAdd(&Aarr[i1], f);
            }
        }
    }
    __syncthreads();
    float norm = s_norm;
    __half* row = g_A + (size_t)k * HWPIX;
    for (int i = t; i < HWPIX; i += 128) {
        int y = i / 96, x = i - y * 96;
        row[i] = __float2half(norm * Ay[y] * Ax[x]);
    }
}

// ---------------- mma.sync fp16 GEMM: out[512,2880] = A[512,9216] @ B[2880,9216]^T ----------------
#define BM 64
#define BN 160
#define BK 64
#define KIT 144                       // 9216/64
#define A_BYTES (BM*BK*2)             // 8192
#define STB (A_BYTES + BN*BK*2)       // 28672 per stage
#define NSTAGE 4
#define SMEM_SZ (NSTAGE*STB + 1024)

__device__ __forceinline__ void cp16(uint32_t d, const void* s) {
    asm volatile("cp.async.cg.shared.global [%0], [%1], 16;\n" :: "r"(d), "l"(s));
}
__device__ __forceinline__ void ldm_x4(uint32_t &r0, uint32_t &r1, uint32_t &r2, uint32_t &r3, uint32_t addr) {
    asm volatile("ldmatrix.sync.aligned.m8n8.x4.shared.b16 {%0,%1,%2,%3}, [%4];\n"
                 : "=r"(r0),"=r"(r1),"=r"(r2),"=r"(r3) : "r"(addr));
}
__device__ __forceinline__ void ldm_x2(uint32_t &r0, uint32_t &r1, uint32_t addr) {
    asm volatile("ldmatrix.sync.aligned.m8n8.x2.shared.b16 {%0,%1}, [%2];\n"
                 : "=r"(r0),"=r"(r1) : "r"(addr));
}
__device__ __forceinline__ void mma16816(float* d, const uint32_t* a, const uint32_t* b) {
    asm volatile("mma.sync.aligned.m16n8k16.row.col.f32.f16.f16.f32 "
                 "{%0,%1,%2,%3}, {%4,%5,%6,%7}, {%8,%9}, {%0,%1,%2,%3};\n"
                 : "+f"(d[0]),"+f"(d[1]),"+f"(d[2]),"+f"(d[3])
                 : "r"(a[0]),"r"(a[1]),"r"(a[2]),"r"(a[3]),"r"(b[0]),"r"(b[1]));
}

__device__ __forceinline__ void load_stage(uint32_t sb, int bm0, int bn0, int kt, int tid) {
    uint32_t aS = sb + (uint32_t)(kt & (NSTAGE-1)) * STB;
    uint32_t bS = aS + A_BYTES;
    int ch = tid & 7, r0 = tid >> 3;
    const __half* ap = g_A + (size_t)bm0 * HWPIX + kt * BK + ch * 8;
    const __half* bp = g_B + (size_t)bn0 * HWPIX + kt * BK + ch * 8;
    #pragma unroll
    for (int r = r0; r < BM; r += 32)
        cp16(aS + (r * 8 + (ch ^ (r & 7))) * 16, ap + (size_t)r * HWPIX);
    #pragma unroll
    for (int r = r0; r < BN; r += 32)
        cp16(bS + (r * 8 + (ch ^ (r & 7))) * 16, bp + (size_t)r * HWPIX);
}

__global__ __launch_bounds__(256, 1) void k_gemm(float* __restrict__ out) {
    extern __shared__ __align__(1024) char smem_raw[];
    uint32_t sb = ((uint32_t)__cvta_generic_to_shared(smem_raw) + 1023) & ~1023u;
    const int tid = threadIdx.x, warp = tid >> 5, lane = tid & 31;
    const int wm = (warp >> 2) * 32;      // 2 M-warps
    const int wn = (warp & 3) * 40;       // 4 N-warps, warp tile 32x40
    const int bm0 = blockIdx.y * BM;
    const int bn0 = blockIdx.x * BN;

    float acc[2][5][4];
    #pragma unroll
    for (int i = 0; i < 2; i++)
        #pragma unroll
        for (int j = 0; j < 5; j++)
            #pragma unroll
            for (int c = 0; c < 4; c++) acc[i][j][c] = 0.f;

    load_stage(sb, bm0, bn0, 0, tid); asm volatile("cp.async.commit_group;" ::: "memory");
    load_stage(sb, bm0, bn0, 1, tid); asm volatile("cp.async.commit_group;" ::: "memory");
    load_stage(sb, bm0, bn0, 2, tid); asm volatile("cp.async.commit_group;" ::: "memory");

    for (int kt = 0; kt < KIT; kt++) {
        if (kt <= KIT - 3)      asm volatile("cp.async.wait_group 2;" ::: "memory");
        else if (kt == KIT - 2) asm volatile("cp.async.wait_group 1;" ::: "memory");
        else                    asm volatile("cp.async.wait_group 0;" ::: "memory");
        __syncthreads();
        if (kt + 3 < KIT) {
            load_stage(sb, bm0, bn0, kt + 3, tid);
            asm volatile("cp.async.commit_group;" ::: "memory");
        }

        const uint32_t aS = sb + (uint32_t)(kt & (NSTAGE-1)) * STB;
        const uint32_t bS = aS + A_BYTES;
        #pragma unroll
        for (int ks = 0; ks < 4; ks++) {
            // A fragments: 2 x (16m x 16k)
            uint32_t a[2][4];
            #pragma unroll
            for (int mt = 0; mt < 2; mt++) {
                int m  = wm + mt * 16 + (lane & 15);
                int kc = ks * 2 + (lane >> 4);
                ldm_x4(a[mt][0], a[mt][1], a[mt][2], a[mt][3],
                       aS + (m * 8 + (kc ^ (m & 7))) * 16);
            }
            // B fragments: 5 x (8n x 16k), K-contiguous rows -> non-trans ldmatrix
            uint32_t b[5][2];
            #pragma unroll
            for (int p = 0; p < 2; p++) {   // frags 2p, 2p+1 via one x4
                int g = lane >> 3;
                int n  = wn + p * 16 + (g >> 1) * 8 + (lane & 7);
                int kc = ks * 2 + (g & 1);
                ldm_x4(b[2*p][0], b[2*p][1], b[2*p+1][0], b[2*p+1][1],
                       bS + (n * 8 + (kc ^ (n & 7))) * 16);
            }
            {   // frag 4 via x2 (lanes 0-15 supply addresses)
                int g = lane >> 3;
                int n  = wn + 32 + (lane & 7);
                int kc = ks * 2 + (g & 1);
                ldm_x2(b[4][0], b[4][1], bS + (n * 8 + (kc ^ (n & 7))) * 16);
            }
            #pragma unroll
            for (int mt = 0; mt < 2; mt++)
                #pragma unroll
                for (int nt = 0; nt < 5; nt++)
                    mma16816(acc[mt][nt], a[mt], b[nt]);
        }
    }

    // Epilogue: direct fp32 stores (all tile dims exact).
    int r0 = lane >> 2, c0 = (lane & 3) * 2;
    #pragma unroll
    for (int mt = 0; mt < 2; mt++) {
        #pragma unroll
        for (int nt = 0; nt < 5; nt++) {
            int m = bm0 + wm + mt * 16 + r0;
            int n = bn0 + wn + nt * 8 + c0;
            *(float2*)&out[(size_t)m       * CTOT + n] = make_float2(acc[mt][nt][0], acc[mt][nt][1]);
            *(float2*)&out[(size_t)(m + 8) * CTOT + n] = make_float2(acc[mt][nt][2], acc[mt][nt][3]);
        }
    }
}

extern "C" void kernel_launch(void* const* d_in, const int* in_sizes, int n_in,
                              void* d_out, int out_size) {
    const float* feat0 = (const float*)d_in[0];
    const float* feat1 = (const float*)d_in[1];
    const float* feat2 = (const float*)d_in[2];
    const float* feat3 = (const float*)d_in[3];
    const float* boxes = (const float*)d_in[4];
    float* out = (float*)d_out;

    cudaFuncSetAttribute(k_gemm, cudaFuncAttributeMaxDynamicSharedMemorySize, SMEM_SZ);

    k_conv0<<<1728, 256>>>((const float4*)feat0);          // rows [0,192)
    k_up<<<384,  256>>>(feat1, 192,  48, 0.5f);            // rows [192,576)
    k_up<<<768,  256>>>(feat2, 576,  24, 0.25f);           // rows [576,1344)
    k_up<<<1536, 256>>>(feat3, 1344, 12, 0.125f);          // rows [1344,2880)
    k_weights<<<NBOX, 128>>>(boxes);
    k_gemm<<<dim3(CTOT / BN, NBOX / BM), 256, SMEM_SZ>>>(out);
}

// round 4
// speedup vs baseline: 1.7012x; 1.3607x over previous
#include <cuda_runtime.h>
#include <cuda_fp16.h>
#include <cstdint>

#define HWPIX 9216
#define CTOT 2880
#define NBOX 512

// Static device scratch. Both operands K-major (K = pixel index).
__device__ __align__(256) __half g_B[(size_t)CTOT * HWPIX];   // [channel][pixel], 53MB
__device__ __align__(256) __half g_A[(size_t)NBOX * HWPIX];   // [sorted box][pixel], 9.4MB
__device__ int g_perm[NBOX];          // sorted slot -> original box index
__device__ int g_ktlo[8], g_kthi[8];  // per 64-box M-tile: K-chunk range

// ---------------- level0: fp32 -> fp16 elementwise into rows [0,192) ----------------
__global__ void k_conv0(const float4* __restrict__ src) {
    int i = blockIdx.x * 256 + threadIdx.x;   // grid sized exactly: 192*9216/4 float4s
    float4 v = src[i];
    __half2* d = reinterpret_cast<__half2*>(g_B);
    d[2 * i]     = __floats2half2_rn(v.x, v.y);
    d[2 * i + 1] = __floats2half2_rn(v.z, v.w);
}

// ---------------- bilinear half-pixel upsample, G channels per block ----------------
// Coordinates depend only on the output pixel -> computed once per thread (x) /
// once per row-pass (y) and reused across G channels. Source planes cached in smem.
template<int HS, int G>
__global__ __launch_bounds__(384) void k_up2(const float* __restrict__ src, int coff, float inv) {
    __shared__ float s[G * HS * HS];
    int c0 = blockIdx.x * G;
    const float4* s4 = (const float4*)(src + (size_t)c0 * HS * HS);
    float4* d4 = (float4*)s;
    for (int i = threadIdx.x; i < G * HS * HS / 4; i += 384) d4[i] = s4[i];
    __syncthreads();

    int xi = threadIdx.x % 48, ty = threadIdx.x / 48;   // 48 x-pairs, 8 rows per pass
    int xa = 2 * xi, xb = xa + 1;
    float Xfa = fminf(fmaxf(((float)xa + 0.5f) * inv - 0.5f, 0.f), (float)(HS - 1));
    float Xfb = fminf(fmaxf(((float)xb + 0.5f) * inv - 0.5f, 0.f), (float)(HS - 1));
    int x0a = min((int)Xfa, HS - 2), x0b = min((int)Xfb, HS - 2);
    float fxa = Xfa - (float)x0a, fxb = Xfb - (float)x0b;

    #pragma unroll
    for (int yp = 0; yp < 12; yp++) {
        int y = yp * 8 + ty;
        float Yf = fminf(fmaxf(((float)y + 0.5f) * inv - 0.5f, 0.f), (float)(HS - 1));
        int y0 = min((int)Yf, HS - 2);
        float fy = Yf - (float)y0;
        #pragma unroll
        for (int c = 0; c < G; c++) {
            const float* P = s + c * HS * HS + y0 * HS;
            float ta = (1.f - fxa) * P[x0a]      + fxa * P[x0a + 1];
            float ba = (1.f - fxa) * P[HS + x0a] + fxa * P[HS + x0a + 1];
            float tb = (1.f - fxb) * P[x0b]      + fxb * P[x0b + 1];
            float bb = (1.f - fxb) * P[HS + x0b] + fxb * P[HS + x0b + 1];
            float va = ta + fy * (ba - ta);
            float vb = tb + fy * (bb - tb);
            __half2* dst = (__half2*)(g_B + (size_t)(coff + c0 + c) * HWPIX + y * 96 + xa);
            *dst = __floats2half2_rn(va, vb);
        }
    }
}

// ---------------- box prep: exact touched-y range, counting sort by y-center, tile K ranges ----
__global__ __launch_bounds__(512) void k_boxprep(const float* __restrict__ boxes) {
    __shared__ int s_lo[NBOX], s_hi[NBOX];
    __shared__ int hist[256], offs[256];
    __shared__ int tlo[8], thi[8];
    int t = threadIdx.x;
    if (t < 256) hist[t] = 0;
    if (t < 8) { tlo[t] = 1 << 30; thi[t] = -1; }
    __syncthreads();

    float y1 = boxes[t * 4 + 1], y2 = boxes[t * 4 + 3];
    float rh = fmaxf(y2 - y1, 1.f);
    float gh = fminf(fmaxf(ceilf(rh / 7.f), 1.f), 8.f);
    float b = rh / 7.f;
    int ymin = 95, ymax = 0;
    #pragma unroll
    for (int pp = 0; pp < 7; pp++)
        #pragma unroll
        for (int ss = 0; ss < 8; ss++) {
            if ((float)ss < gh) {
                float coord = y1 + (float)pp * b + ((float)ss + 0.5f) * (b / gh);
                if (!(coord < -1.f || coord > 96.f)) {
                    float c = fmaxf(coord, 0.f);
                    int i0 = (int)floorf(c);
                    int i1 = (i0 >= 95) ? 95 : i0 + 1;
                    if (i0 > 95) i0 = 95;
                    ymin = min(ymin, i0);
                    ymax = max(ymax, i1);
                }
            }
        }
    s_lo[t] = (ymin * 96) / 64;
    s_hi[t] = (ymax * 96 + 95) / 64;
    int key = ymin + ymax;   // ~2*y-center, in [0,190]
    atomicAdd(&hist[key], 1);
    __syncthreads();
    if (t == 0) { int acc = 0; for (int i = 0; i < 256; i++) { offs[i] = acc; acc += hist[i]; } }
    __syncthreads();
    int pos = atomicAdd(&offs[key], 1);
    g_perm[pos] = t;
    atomicMin(&tlo[pos >> 6], s_lo[t]);
    atomicMax(&thi[pos >> 6], s_hi[t]);
    __syncthreads();
    if (t < 8) { g_ktlo[t] = tlo[t]; g_kthi[t] = thi[t]; }
}

// ---------------- per-box separable ROI-align weights: W[y,x] = norm * Ay[y] * Ax[x] ----------------
__global__ void k_weights(const float* __restrict__ boxes) {
    __shared__ float Ax[96], Ay[96];
    __shared__ float s_norm;
    int slot = blockIdx.x;
    int k = g_perm[slot];
    int t = threadIdx.x;  // 128 threads
    if (t < 96) { Ax[t] = 0.f; Ay[t] = 0.f; }
    float x1 = boxes[k*4+0], y1 = boxes[k*4+1];
    float x2 = boxes[k*4+2], y2 = boxes[k*4+3];
    float rw = fmaxf(x2 - x1, 1.0f), rh = fmaxf(y2 - y1, 1.0f);
    float gw = fminf(fmaxf(ceilf(rw / 7.0f), 1.0f), 8.0f);
    float gh = fminf(fmaxf(ceilf(rh / 7.0f), 1.0f), 8.0f);
    if (t == 0) s_norm = 1.0f / (gh * gw * 49.0f);
    __syncthreads();
    if (t < 112) {
        int isY = t >= 56;
        int i = isY ? t - 56 : t;
        int pp = i >> 3, ss = i & 7;
        float lo = isY ? y1 : x1;
        float sz = isY ? rh : rw;
        float g  = isY ? gh : gw;
        float* Aarr = isY ? Ay : Ax;
        if ((float)ss < g) {
            float b = sz / 7.0f;
            float coord = lo + (float)pp * b + ((float)ss + 0.5f) * (b / g);
            if (!(coord < -1.0f || coord > 96.0f)) {
                float c = fmaxf(coord, 0.0f);
                int i0 = (int)floorf(c);
                int i1; float f;
                if (i0 >= 95) { i0 = 95; i1 = 95; f = 0.f; }
                else          { i1 = i0 + 1; f = c - (float)i0; }
                atomicAdd(&Aarr[i0], 1.0f - f);
                atomicAdd(&Aarr[i1], f);
            }
        }
    }
    __syncthreads();
    float norm = s_norm;
    __half2* row = (__half2*)(g_A + (size_t)slot * HWPIX);
    for (int j = t; j < HWPIX / 2; j += 128) {
        int e = 2 * j;
        int y = e / 96, x = e - y * 96;
        float v = norm * Ay[y];
        row[j] = __floats2half2_rn(v * Ax[x], v * Ax[x + 1]);
    }
}

// ---------------- mma.sync fp16 GEMM with per-M-tile K-range skipping ----------------
#define BM 64
#define BN 160
#define BK 64
#define A_BYTES (BM*BK*2)             // 8192
#define STB (A_BYTES + BN*BK*2)       // 28672 per stage
#define NSTAGE 4
#define SMEM_SZ (NSTAGE*STB + 1024)

__device__ __forceinline__ void cp16(uint32_t d, const void* s) {
    asm volatile("cp.async.cg.shared.global [%0], [%1], 16;\n" :: "r"(d), "l"(s));
}
__device__ __forceinline__ void ldm_x4(uint32_t &r0, uint32_t &r1, uint32_t &r2, uint32_t &r3, uint32_t addr) {
    asm volatile("ldmatrix.sync.aligned.m8n8.x4.shared.b16 {%0,%1,%2,%3}, [%4];\n"
                 : "=r"(r0),"=r"(r1),"=r"(r2),"=r"(r3) : "r"(addr));
}
__device__ __forceinline__ void ldm_x2(uint32_t &r0, uint32_t &r1, uint32_t addr) {
    asm volatile("ldmatrix.sync.aligned.m8n8.x2.shared.b16 {%0,%1}, [%2];\n"
                 : "=r"(r0),"=r"(r1) : "r"(addr));
}
__device__ __forceinline__ void mma16816(float* d, const uint32_t* a, const uint32_t* b) {
    asm volatile("mma.sync.aligned.m16n8k16.row.col.f32.f16.f16.f32 "
                 "{%0,%1,%2,%3}, {%4,%5,%6,%7}, {%8,%9}, {%0,%1,%2,%3};\n"
                 : "+f"(d[0]),"+f"(d[1]),"+f"(d[2]),"+f"(d[3])
                 : "r"(a[0]),"r"(a[1]),"r"(a[2]),"r"(a[3]),"r"(b[0]),"r"(b[1]));
}

__device__ __forceinline__ void load_stage(uint32_t sb, int bm0, int bn0, int kt, int slot, int tid) {
    uint32_t aS = sb + (uint32_t)slot * STB;
    uint32_t bS = aS + A_BYTES;
    int ch = tid & 7, r0 = tid >> 3;
    const __half* ap = g_A + (size_t)bm0 * HWPIX + kt * BK + ch * 8;
    const __half* bp = g_B + (size_t)bn0 * HWPIX + kt * BK + ch * 8;
    #pragma unroll
    for (int r = r0; r < BM; r += 32)
        cp16(aS + (r * 8 + (ch ^ (r & 7))) * 16, ap + (size_t)r * HWPIX);
    #pragma unroll
    for (int r = r0; r < BN; r += 32)
        cp16(bS + (r * 8 + (ch ^ (r & 7))) * 16, bp + (size_t)r * HWPIX);
}

__global__ __launch_bounds__(256, 1) void k_gemm(float* __restrict__ out) {
    extern __shared__ __align__(1024) char smem_raw[];
    uint32_t sb = ((uint32_t)__cvta_generic_to_shared(smem_raw) + 1023) & ~1023u;
    const int tid = threadIdx.x, warp = tid >> 5, lane = tid & 31;
    const int wm = (warp >> 2) * 32;      // 2 M-warps
    const int wn = (warp & 3) * 40;       // 4 N-warps, warp tile 32x40
    const int bm0 = blockIdx.y * BM;
    const int bn0 = blockIdx.x * BN;
    const int lo  = g_ktlo[blockIdx.y];
    const int nk  = g_kthi[blockIdx.y] - lo + 1;

    float acc[2][5][4];
    #pragma unroll
    for (int i = 0; i < 2; i++)
        #pragma unroll
        for (int j = 0; j < 5; j++)
            #pragma unroll
            for (int c = 0; c < 4; c++) acc[i][j][c] = 0.f;

    #pragma unroll
    for (int i = 0; i < 3; i++) {
        if (i < nk) {
            load_stage(sb, bm0, bn0, lo + i, i, tid);
            asm volatile("cp.async.commit_group;" ::: "memory");
        }
    }

    for (int j = 0; j < nk; j++) {
        if (j <= nk - 3)      asm volatile("cp.async.wait_group 2;" ::: "memory");
        else if (j == nk - 2) asm volatile("cp.async.wait_group 1;" ::: "memory");
        else                  asm volatile("cp.async.wait_group 0;" ::: "memory");
        __syncthreads();
        if (j + 3 < nk) {
            load_stage(sb, bm0, bn0, lo + j + 3, (j + 3) & 3, tid);
            asm volatile("cp.async.commit_group;" ::: "memory");
        }

        const uint32_t aS = sb + (uint32_t)(j & 3) * STB;
        const uint32_t bS = aS + A_BYTES;
        #pragma unroll
        for (int ks = 0; ks < 4; ks++) {
            uint32_t a[2][4];
            #pragma unroll
            for (int mt = 0; mt < 2; mt++) {
                int m  = wm + mt * 16 + (lane & 15);
                int kc = ks * 2 + (lane >> 4);
                ldm_x4(a[mt][0], a[mt][1], a[mt][2], a[mt][3],
                       aS + (m * 8 + (kc ^ (m & 7))) * 16);
            }
            uint32_t b[5][2];
            #pragma unroll
            for (int p = 0; p < 2; p++) {
                int g = lane >> 3;
                int n  = wn + p * 16 + (g >> 1) * 8 + (lane & 7);
                int kc = ks * 2 + (g & 1);
                ldm_x4(b[2*p][0], b[2*p][1], b[2*p+1][0], b[2*p+1][1],
                       bS + (n * 8 + (kc ^ (n & 7))) * 16);
            }
            {
                int g = lane >> 3;
                int n  = wn + 32 + (lane & 7);
                int kc = ks * 2 + (g & 1);
                ldm_x2(b[4][0], b[4][1], bS + (n * 8 + (kc ^ (n & 7))) * 16);
            }
            #pragma unroll
            for (int mt = 0; mt < 2; mt++)
                #pragma unroll
                for (int nt = 0; nt < 5; nt++)
                    mma16816(acc[mt][nt], a[mt], b[nt]);
        }
    }

    // Epilogue: scatter rows through perm back to original box order.
    int r0 = lane >> 2, c0 = (lane & 3) * 2;
    #pragma unroll
    for (int mt = 0; mt < 2; mt++) {
        int mA = bm0 + wm + mt * 16 + r0;
        int rowA = g_perm[mA];
        int rowB = g_perm[mA + 8];
        #pragma unroll
        for (int nt = 0; nt < 5; nt++) {
            int n = bn0 + wn + nt * 8 + c0;
            *(float2*)&out[(size_t)rowA * CTOT + n] = make_float2(acc[mt][nt][0], acc[mt][nt][1]);
            *(float2*)&out[(size_t)rowB * CTOT + n] = make_float2(acc[mt][nt][2], acc[mt][nt][3]);
        }
    }
}

extern "C" void kernel_launch(void* const* d_in, const int* in_sizes, int n_in,
                              void* d_out, int out_size) {
    const float* feat0 = (const float*)d_in[0];
    const float* feat1 = (const float*)d_in[1];
    const float* feat2 = (const float*)d_in[2];
    const float* feat3 = (const float*)d_in[3];
    const float* boxes = (const float*)d_in[4];
    float* out = (float*)d_out;

    cudaFuncSetAttribute(k_gemm, cudaFuncAttributeMaxDynamicSharedMemorySize, SMEM_SZ);

    k_conv0<<<1728, 256>>>((const float4*)feat0);            // rows [0,192)
    k_up2<48, 2><<<192, 384>>>(feat1, 192,  0.5f);           // rows [192,576)
    k_up2<24, 4><<<192, 384>>>(feat2, 576,  0.25f);          // rows [576,1344)
    k_up2<12, 8><<<192, 384>>>(feat3, 1344, 0.125f);         // rows [1344,2880)
    k_boxprep<<<1, 512>>>(boxes);
    k_weights<<<NBOX, 128>>>(boxes);
    k_gemm<<<dim3(CTOT / BN, NBOX / BM), 256, SMEM_SZ>>>(out);
}

// round 5
// speedup vs baseline: 1.9792x; 1.1634x over previous
#include <cuda_runtime.h>
#include <cuda_fp16.h>
#include <cstdint>

#define HWPIX 9216
#define CTOT 2880
#define NBOX 512

// Static device scratch. Both operands K-major (K = pixel index).
__device__ __align__(256) __half g_B[(size_t)CTOT * HWPIX];   // [channel][pixel], 53MB
__device__ __align__(256) __half g_A[(size_t)NBOX * HWPIX];   // [sorted box][pixel], 9.4MB
__device__ int g_perm[NBOX];          // sorted slot -> original box index
__device__ int g_ktlo[8], g_kthi[8];  // per 64-box M-tile: K-chunk range

// ---------------- level0: fp32 -> fp16, 8 halves per thread ----------------
__global__ void k_conv0(const float4* __restrict__ src) {
    int i = blockIdx.x * 256 + threadIdx.x;   // grid exact: 192*9216/8 threads
    float4 a = src[2 * i], b = src[2 * i + 1];
    __half2 h[4];
    h[0] = __floats2half2_rn(a.x, a.y);
    h[1] = __floats2half2_rn(a.z, a.w);
    h[2] = __floats2half2_rn(b.x, b.y);
    h[3] = __floats2half2_rn(b.z, b.w);
    reinterpret_cast<uint4*>(g_B)[i] = *reinterpret_cast<uint4*>(h);
}

// ---------------- bilinear half-pixel upsample: 8 outputs/thread, const fx tables ----------
// r = 96/HS is an integer, so within an aligned 8-output x-segment the source-index
// offset q(i) and fraction fx(i) are compile-time constants. Per row-pair a thread
// loads only 8/r+2 source values per row and issues one 16B store per channel.
template<int HS, int G>
__global__ __launch_bounds__(384) void k_up3(const float* __restrict__ src, int coff) {
    constexpr int R  = 96 / HS;
    constexpr int NV = 8 / R + 2;
    constexpr float INV = (float)HS / 96.0f;
    __shared__ float s[G * HS * HS];
    int c0 = blockIdx.x * G;
    const float4* s4 = (const float4*)(src + (size_t)c0 * HS * HS);
    float4* d4 = (float4*)s;
    for (int i = threadIdx.x; i < G * HS * HS / 4; i += 384) d4[i] = s4[i];
    __syncthreads();

    #pragma unroll
    for (int pass = 0; pass < 3; pass++) {
        int pos = pass * 384 + threadIdx.x;     // 1152 = 96 y x 12 segments
        int y = pos / 12, seg = pos % 12;
        int s0 = seg * (HS / 12);
        float Yf = fminf(fmaxf(((float)y + 0.5f) * INV - 0.5f, 0.f), (float)(HS - 1));
        int y0 = min((int)Yf, HS - 2);
        float fy = Yf - (float)y0;
        int xidx[NV];
        #pragma unroll
        for (int j = 0; j < NV; j++) xidx[j] = min(max(s0 - 1 + j, 0), HS - 1);

        #pragma unroll
        for (int c = 0; c < G; c++) {
            const float* P = s + c * HS * HS + y0 * HS;
            float v[NV], w[NV];
            #pragma unroll
            for (int j = 0; j < NV; j++) { v[j] = P[xidx[j]]; w[j] = P[HS + xidx[j]]; }
            __align__(16) __half h[8];
            #pragma unroll
            for (int i = 0; i < 8; i++) {
                constexpr int TWO_R = 2 * R;
                const int qn = 2 * i + 1 - R;
                const int q  = (qn >= 0) ? (qn / TWO_R) : -1;
                const float fx = (float)(qn - TWO_R * q) / (float)TWO_R;
                const int j = q + 1;
                float top = v[j] + fx * (v[j + 1] - v[j]);
                float bot = w[j] + fx * (w[j + 1] - w[j]);
                h[i] = __float2half(top + fy * (bot - top));
            }
            *(uint4*)(g_B + (size_t)(coff + c0 + c) * HWPIX + y * 96 + seg * 8) =
                *reinterpret_cast<uint4*>(h);
        }
    }
}

// ---------------- box prep: exact touched-y range, counting sort by y-center, tile K ranges ----
__global__ __launch_bounds__(512) void k_boxprep(const float* __restrict__ boxes) {
    __shared__ int s_lo[NBOX], s_hi[NBOX];
    __shared__ int hist[256], offs[256];
    __shared__ int tlo[8], thi[8];
    int t = threadIdx.x;
    if (t < 256) hist[t] = 0;
    if (t < 8) { tlo[t] = 1 << 30; thi[t] = -1; }
    __syncthreads();

    float y1 = boxes[t * 4 + 1], y2 = boxes[t * 4 + 3];
    float rh = fmaxf(y2 - y1, 1.f);
    float gh = fminf(fmaxf(ceilf(rh / 7.f), 1.f), 8.f);
    float b = rh / 7.f;
    int ymin = 95, ymax = 0;
    #pragma unroll
    for (int pp = 0; pp < 7; pp++)
        #pragma unroll
        for (int ss = 0; ss < 8; ss++) {
            if ((float)ss < gh) {
                float coord = y1 + (float)pp * b + ((float)ss + 0.5f) * (b / gh);
                if (!(coord < -1.f || coord > 96.f)) {
                    float c = fmaxf(coord, 0.f);
                    int i0 = (int)floorf(c);
                    int i1 = (i0 >= 95) ? 95 : i0 + 1;
                    if (i0 > 95) i0 = 95;
                    ymin = min(ymin, i0);
                    ymax = max(ymax, i1);
                }
            }
        }
    s_lo[t] = (ymin * 96) / 64;
    s_hi[t] = (ymax * 96 + 95) / 64;
    int key = ymin + ymax;   // ~2*y-center, in [0,190]
    atomicAdd(&hist[key], 1);
    __syncthreads();
    if (t == 0) { int acc = 0; for (int i = 0; i < 256; i++) { offs[i] = acc; acc += hist[i]; } }
    __syncthreads();
    int pos = atomicAdd(&offs[key], 1);
    g_perm[pos] = t;
    atomicMin(&tlo[pos >> 6], s_lo[t]);
    atomicMax(&thi[pos >> 6], s_hi[t]);
    __syncthreads();
    if (t < 8) { g_ktlo[t] = tlo[t]; g_kthi[t] = thi[t]; }
}

// ---------------- per-box separable weights, writing only the tile's K-range ----------------
__global__ void k_weights(const float* __restrict__ boxes) {
    __shared__ float Ax[96], Ay[96];
    __shared__ float s_norm;
    int slot = blockIdx.x;
    int k = g_perm[slot];
    int t = threadIdx.x;  // 128 threads
    if (t < 96) { Ax[t] = 0.f; Ay[t] = 0.f; }
    float x1 = boxes[k*4+0], y1 = boxes[k*4+1];
    float x2 = boxes[k*4+2], y2 = boxes[k*4+3];
    float rw = fmaxf(x2 - x1, 1.0f), rh = fmaxf(y2 - y1, 1.0f);
    float gw = fminf(fmaxf(ceilf(rw / 7.0f), 1.0f), 8.0f);
    float gh = fminf(fmaxf(ceilf(rh / 7.0f), 1.0f), 8.0f);
    if (t == 0) s_norm = 1.0f / (gh * gw * 49.0f);
    __syncthreads();
    if (t < 112) {
        int isY = t >= 56;
        int i = isY ? t - 56 : t;
        int pp = i >> 3, ss = i & 7;
        float lo = isY ? y1 : x1;
        float sz = isY ? rh : rw;
        float g  = isY ? gh : gw;
        float* Aarr = isY ? Ay : Ax;
        if ((float)ss < g) {
            float b = sz / 7.0f;
            float coord = lo + (float)pp * b + ((float)ss + 0.5f) * (b / g);
            if (!(coord < -1.0f || coord > 96.0f)) {
                float c = fmaxf(coord, 0.0f);
                int i0 = (int)floorf(c);
                int i1; float f;
                if (i0 >= 95) { i0 = 95; i1 = 95; f = 0.f; }
                else          { i1 = i0 + 1; f = c - (float)i0; }
                atomicAdd(&Aarr[i0], 1.0f - f);
                atomicAdd(&Aarr[i1], f);
            }
        }
    }
    __syncthreads();
    float norm = s_norm;
    // Only pixels inside this tile's K-chunk union are ever read by the GEMM;
    // g_A is zero-initialized and inputs are fixed across replays.
    int plo = g_ktlo[slot >> 6] * 64;
    int phi = (g_kthi[slot >> 6] + 1) * 64;
    __half* row = g_A + (size_t)slot * HWPIX;
    for (int e = plo + t * 8; e < phi; e += 128 * 8) {
        int y = e / 96, x = e - y * 96;       // 8-aligned segments never cross rows
        float vy = norm * Ay[y];
        __align__(16) __half h[8];
        #pragma unroll
        for (int i = 0; i < 8; i++) h[i] = __float2half(vy * Ax[x + i]);
        *(uint4*)(row + e) = *reinterpret_cast<uint4*>(h);
    }
}

// ---------------- mma.sync fp16 GEMM with per-M-tile K-range skipping ----------------
#define BM 64
#define BN 160
#define BK 64
#define A_BYTES (BM*BK*2)             // 8192
#define STB (A_BYTES + BN*BK*2)       // 28672 per stage
#define NSTAGE 4
#define SMEM_SZ (NSTAGE*STB + 1024)

__device__ __forceinline__ void cp16(uint32_t d, const void* s) {
    asm volatile("cp.async.cg.shared.global [%0], [%1], 16;\n" :: "r"(d), "l"(s));
}
__device__ __forceinline__ void ldm_x4(uint32_t &r0, uint32_t &r1, uint32_t &r2, uint32_t &r3, uint32_t addr) {
    asm volatile("ldmatrix.sync.aligned.m8n8.x4.shared.b16 {%0,%1,%2,%3}, [%4];\n"
                 : "=r"(r0),"=r"(r1),"=r"(r2),"=r"(r3) : "r"(addr));
}
__device__ __forceinline__ void ldm_x2(uint32_t &r0, uint32_t &r1, uint32_t addr) {
    asm volatile("ldmatrix.sync.aligned.m8n8.x2.shared.b16 {%0,%1}, [%2];\n"
                 : "=r"(r0),"=r"(r1) : "r"(addr));
}
__device__ __forceinline__ void mma16816(float* d, const uint32_t* a, const uint32_t* b) {
    asm volatile("mma.sync.aligned.m16n8k16.row.col.f32.f16.f16.f32 "
                 "{%0,%1,%2,%3}, {%4,%5,%6,%7}, {%8,%9}, {%0,%1,%2,%3};\n"
                 : "+f"(d[0]),"+f"(d[1]),"+f"(d[2]),"+f"(d[3])
                 : "r"(a[0]),"r"(a[1]),"r"(a[2]),"r"(a[3]),"r"(b[0]),"r"(b[1]));
}

__device__ __forceinline__ void load_stage(uint32_t sb, int bm0, int bn0, int kt, int slot, int tid) {
    uint32_t aS = sb + (uint32_t)slot * STB;
    uint32_t bS = aS + A_BYTES;
    int ch = tid & 7, r0 = tid >> 3;
    const __half* ap = g_A + (size_t)bm0 * HWPIX + kt * BK + ch * 8;
    const __half* bp = g_B + (size_t)bn0 * HWPIX + kt * BK + ch * 8;
    #pragma unroll
    for (int r = r0; r < BM; r += 32)
        cp16(aS + (r * 8 + (ch ^ (r & 7))) * 16, ap + (size_t)r * HWPIX);
    #pragma unroll
    for (int r = r0; r < BN; r += 32)
        cp16(bS + (r * 8 + (ch ^ (r & 7))) * 16, bp + (size_t)r * HWPIX);
}

__global__ __launch_bounds__(256, 1) void k_gemm(float* __restrict__ out) {
    extern __shared__ __align__(1024) char smem_raw[];
    uint32_t sb = ((uint32_t)__cvta_generic_to_shared(smem_raw) + 1023) & ~1023u;
    const int tid = threadIdx.x, warp = tid >> 5, lane = tid & 31;
    const int wm = (warp >> 2) * 32;      // 2 M-warps
    const int wn = (warp & 3) * 40;       // 4 N-warps, warp tile 32x40
    const int bm0 = blockIdx.y * BM;
    const int bn0 = blockIdx.x * BN;
    const int lo  = g_ktlo[blockIdx.y];
    const int nk  = g_kthi[blockIdx.y] - lo + 1;

    float acc[2][5][4];
    #pragma unroll
    for (int i = 0; i < 2; i++)
        #pragma unroll
        for (int j = 0; j < 5; j++)
            #pragma unroll
            for (int c = 0; c < 4; c++) acc[i][j][c] = 0.f;

    #pragma unroll
    for (int i = 0; i < 3; i++) {
        if (i < nk) {
            load_stage(sb, bm0, bn0, lo + i, i, tid);
            asm volatile("cp.async.commit_group;" ::: "memory");
        }
    }

    for (int j = 0; j < nk; j++) {
        if (j <= nk - 3)      asm volatile("cp.async.wait_group 2;" ::: "memory");
        else if (j == nk - 2) asm volatile("cp.async.wait_group 1;" ::: "memory");
        else                  asm volatile("cp.async.wait_group 0;" ::: "memory");
        __syncthreads();
        if (j + 3 < nk) {
            load_stage(sb, bm0, bn0, lo + j + 3, (j + 3) & 3, tid);
            asm volatile("cp.async.commit_group;" ::: "memory");
        }

        const uint32_t aS = sb + (uint32_t)(j & 3) * STB;
        const uint32_t bS = aS + A_BYTES;
        #pragma unroll
        for (int ks = 0; ks < 4; ks++) {
            uint32_t a[2][4];
            #pragma unroll
            for (int mt = 0; mt < 2; mt++) {
                int m  = wm + mt * 16 + (lane & 15);
                int kc = ks * 2 + (lane >> 4);
                ldm_x4(a[mt][0], a[mt][1], a[mt][2], a[mt][3],
                       aS + (m * 8 + (kc ^ (m & 7))) * 16);
            }
            uint32_t b[5][2];
            #pragma unroll
            for (int p = 0; p < 2; p++) {
                int g = lane >> 3;
                int n  = wn + p * 16 + (g >> 1) * 8 + (lane & 7);
                int kc = ks * 2 + (g & 1);
                ldm_x4(b[2*p][0], b[2*p][1], b[2*p+1][0], b[2*p+1][1],
                       bS + (n * 8 + (kc ^ (n & 7))) * 16);
            }
            {
                int g = lane >> 3;
                int n  = wn + 32 + (lane & 7);
                int kc = ks * 2 + (g & 1);
                ldm_x2(b[4][0], b[4][1], bS + (n * 8 + (kc ^ (n & 7))) * 16);
            }
            #pragma unroll
            for (int mt = 0; mt < 2; mt++)
                #pragma unroll
                for (int nt = 0; nt < 5; nt++)
                    mma16816(acc[mt][nt], a[mt], b[nt]);
        }
    }

    // Epilogue: scatter rows through perm back to original box order.
    int r0 = lane >> 2, c0 = (lane & 3) * 2;
    #pragma unroll
    for (int mt = 0; mt < 2; mt++) {
        int mA = bm0 + wm + mt * 16 + r0;
        int rowA = g_perm[mA];
        int rowB = g_perm[mA + 8];
        #pragma unroll
        for (int nt = 0; nt < 5; nt++) {
            int n = bn0 + wn + nt * 8 + c0;
            *(float2*)&out[(size_t)rowA * CTOT + n] = make_float2(acc[mt][nt][0], acc[mt][nt][1]);
            *(float2*)&out[(size_t)rowB * CTOT + n] = make_float2(acc[mt][nt][2], acc[mt][nt][3]);
        }
    }
}

extern "C" void kernel_launch(void* const* d_in, const int* in_sizes, int n_in,
                              void* d_out, int out_size) {
    const float* feat0 = (const float*)d_in[0];
    const float* feat1 = (const float*)d_in[1];
    const float* feat2 = (const float*)d_in[2];
    const float* feat3 = (const float*)d_in[3];
    const float* boxes = (const float*)d_in[4];
    float* out = (float*)d_out;

    cudaFuncSetAttribute(k_gemm, cudaFuncAttributeMaxDynamicSharedMemorySize, SMEM_SZ);

    k_conv0<<<864, 256>>>((const float4*)feat0);             // rows [0,192)
    k_up3<48, 1><<<384, 384>>>(feat1, 192);                  // rows [192,576)
    k_up3<24, 2><<<384, 384>>>(feat2, 576);                  // rows [576,1344)
    k_up3<12, 4><<<384, 384>>>(feat3, 1344);                 // rows [1344,2880)
    k_boxprep<<<1, 512>>>(boxes);
    k_weights<<<NBOX, 128>>>(boxes);
    k_gemm<<<dim3(CTOT / BN, NBOX / BM), 256, SMEM_SZ>>>(out);
}

// round 6
// speedup vs baseline: 4.3151x; 2.1803x over previous
#include <cuda_runtime.h>
#include <cuda_fp16.h>
#include <cstdint>

#define CTOT 2880
#define NBOX 512

// Raw features in fp16, K-major per level (natural [C][pixel] layout).
__device__ __align__(256) __half g_F0[192 * 9216];
__device__ __align__(256) __half g_F1[384 * 2304];
__device__ __align__(256) __half g_F2[768 * 576];
__device__ __align__(256) __half g_F3[1536 * 192];   // 144 + 48 zero pad
// Projected ROI weight rows per level (sorted box order).
__device__ __align__(256) __half g_A0[NBOX * 9216];
__device__ __align__(256) __half g_A1[NBOX * 2304];
__device__ __align__(256) __half g_A2[NBOX * 576];
__device__ __align__(256) __half g_A3[NBOX * 192];
__device__ int g_perm[NBOX];          // sorted slot -> original box index
__device__ int g_ktlo[8], g_kthi[8];  // per 64-box M-tile: level-0 K-chunk range

// ---------------- fp32 -> fp16 convert, 8 halves/thread ----------------
template<int L>
__global__ void k_cvt(const float4* __restrict__ src) {
    int i = blockIdx.x * 256 + threadIdx.x;
    float4 a = src[2 * i], b = src[2 * i + 1];
    __half2 h[4];
    h[0] = __floats2half2_rn(a.x, a.y);
    h[1] = __floats2half2_rn(a.z, a.w);
    h[2] = __floats2half2_rn(b.x, b.y);
    h[3] = __floats2half2_rn(b.z, b.w);
    __half* dst = (L == 0) ? g_F0 : (L == 1) ? g_F1 : g_F2;
    reinterpret_cast<uint4*>(dst)[i] = *reinterpret_cast<uint4*>(h);
}

// level3: [1536][144] -> [1536][192] with zero pad
__global__ void k_cvt3(const float* __restrict__ src) {
    int c = blockIdx.x, j = threadIdx.x;   // grid 1536 x 192
    g_F3[c * 192 + j] = (j < 144) ? __float2half(src[c * 144 + j]) : __half(0);
}

// zero the split-K output stripe: columns [0,576) of out[512][2880]
__global__ void k_zero576(float4* __restrict__ out) {
    int i = blockIdx.x * 256 + threadIdx.x;    // 288 blocks: 512*144 float4s
    int k = i / 144, c4 = i % 144;
    out[k * 720 + c4] = make_float4(0.f, 0.f, 0.f, 0.f);
}

// ---------------- box prep: touched-y range, counting sort by y-center, tile K ranges ----
__global__ __launch_bounds__(512) void k_boxprep(const float* __restrict__ boxes) {
    __shared__ int hist[256], offs[256];
    __shared__ int tlo[8], thi[8];
    int t = threadIdx.x;
    if (t < 256) hist[t] = 0;
    if (t < 8) { tlo[t] = 1 << 30; thi[t] = -1; }
    __syncthreads();

    float y1 = boxes[t * 4 + 1], y2 = boxes[t * 4 + 3];
    float rh = fmaxf(y2 - y1, 1.f);
    float gh = fminf(fmaxf(ceilf(rh / 7.f), 1.f), 8.f);
    float b = rh / 7.f;
    int ymin = 95, ymax = 0;
    #pragma unroll
    for (int pp = 0; pp < 7; pp++)
        #pragma unroll
        for (int ss = 0; ss < 8; ss++) {
            if ((float)ss < gh) {
                float coord = y1 + (float)pp * b + ((float)ss + 0.5f) * (b / gh);
                if (!(coord < -1.f || coord > 96.f)) {
                    float c = fmaxf(coord, 0.f);
                    int i0 = (int)floorf(c);
                    int i1 = (i0 >= 95) ? 95 : i0 + 1;
                    if (i0 > 95) i0 = 95;
                    ymin = min(ymin, i0);
                    ymax = max(ymax, i1);
                }
            }
        }
    int mylo = (ymin * 96) / 64;
    int myhi = (ymax * 96 + 95) / 64;
    int key = ymin + ymax;   // ~2*y-center
    atomicAdd(&hist[key], 1);
    __syncthreads();
    if (t == 0) { int acc = 0; for (int i = 0; i < 256; i++) { offs[i] = acc; acc += hist[i]; } }
    __syncthreads();
    int pos = atomicAdd(&offs[key], 1);
    g_perm[pos] = t;
    atomicMin(&tlo[pos >> 6], mylo);
    atomicMax(&thi[pos >> 6], myhi);
    __syncthreads();
    if (t < 8) { g_ktlo[t] = tlo[t]; g_kthi[t] = thi[t]; }
}

// ---------------- per-box weights: build Ax/Ay, project through upsample, write A0..A3 ----
__global__ void k_weights(const float* __restrict__ boxes) {
    __shared__ float Ax[96], Ay[96];
    __shared__ float AxP[84], AyP[84];   // [0,48) L1, [48,72) L2, [72,84) L3
    __shared__ float s_norm;
    int slot = blockIdx.x;
    int k = g_perm[slot];
    int t = threadIdx.x;  // 128 threads
    if (t < 96) { Ax[t] = 0.f; Ay[t] = 0.f; }
    if (t < 84) { AxP[t] = 0.f; AyP[t] = 0.f; }
    float x1 = boxes[k*4+0], y1 = boxes[k*4+1];
    float x2 = boxes[k*4+2], y2 = boxes[k*4+3];
    float rw = fmaxf(x2 - x1, 1.0f), rh = fmaxf(y2 - y1, 1.0f);
    float gw = fminf(fmaxf(ceilf(rw / 7.0f), 1.0f), 8.0f);
    float gh = fminf(fmaxf(ceilf(rh / 7.0f), 1.0f), 8.0f);
    if (t == 0) s_norm = 1.0f / (gh * gw * 49.0f);
    __syncthreads();
    if (t < 112) {
        int isY = t >= 56;
        int i = isY ? t - 56 : t;
        int pp = i >> 3, ss = i & 7;
        float lo = isY ? y1 : x1;
        float sz = isY ? rh : rw;
        float g  = isY ? gh : gw;
        float* Aarr = isY ? Ay : Ax;
        if ((float)ss < g) {
            float b = sz / 7.0f;
            float coord = lo + (float)pp * b + ((float)ss + 0.5f) * (b / g);
            if (!(coord < -1.0f || coord > 96.0f)) {
                float c = fmaxf(coord, 0.0f);
                int i0 = (int)floorf(c);
                int i1; float f;
                if (i0 >= 95) { i0 = 95; i1 = 95; f = 0.f; }
                else          { i1 = i0 + 1; f = c - (float)i0; }
                atomicAdd(&Aarr[i0], 1.0f - f);
                atomicAdd(&Aarr[i1], f);
            }
        }
    }
    __syncthreads();
    // Project through the bilinear upsample: A_l = U_l^T A (separable, per axis).
    if (t < 96) {
        float axv = Ax[t], ayv = Ay[t];
        auto proj = [&](float* dst, float v, int HS, float sc) {
            float Xf = ((float)t + 0.5f) * sc - 0.5f;
            float Xc = fminf(fmaxf(Xf, 0.f), (float)(HS - 1));
            int x0 = min((int)Xc, HS - 2);
            float f = Xc - (float)x0;
            atomicAdd(dst + x0, v * (1.f - f));
            atomicAdd(dst + x0 + 1, v * f);
        };
        proj(AxP + 0,  axv, 48, 0.5f);   proj(AyP + 0,  ayv, 48, 0.5f);
        proj(AxP + 48, axv, 24, 0.25f);  proj(AyP + 48, ayv, 24, 0.25f);
        proj(AxP + 72, axv, 12, 0.125f); proj(AyP + 72, ayv, 12, 0.125f);
    }
    __syncthreads();
    float norm = s_norm;
    // A0: write only this tile's K-chunk union (all the GEMM ever reads).
    {
        int plo = g_ktlo[slot >> 6] * 64;
        int phi = (g_kthi[slot >> 6] + 1) * 64;
        __half* row = g_A0 + (size_t)slot * 9216;
        for (int e = plo + t * 8; e < phi; e += 128 * 8) {
            int y = e / 96, x = e - y * 96;
            float vy = norm * Ay[y];
            __align__(16) __half h[8];
            #pragma unroll
            for (int i = 0; i < 8; i++) h[i] = __float2half(vy * Ax[x + i]);
            *(uint4*)(row + e) = *reinterpret_cast<uint4*>(h);
        }
    }
    // A1: 48x48
    {
        __half* row = g_A1 + (size_t)slot * 2304;
        for (int e = t * 8; e < 2304; e += 128 * 8) {
            int y = e / 48, x = e - y * 48;
            float vy = norm * AyP[y];
            __align__(16) __half h[8];
            #pragma unroll
            for (int i = 0; i < 8; i++) h[i] = __float2half(vy * AxP[x + i]);
            *(uint4*)(row + e) = *reinterpret_cast<uint4*>(h);
        }
    }
    // A2: 24x24
    {
        __half* row = g_A2 + (size_t)slot * 576;
        for (int e = t * 8; e < 576; e += 128 * 8) {
            int y = e / 24, x = e - y * 24;
            float vy = norm * AyP[48 + y];
            __align__(16) __half h[8];
            #pragma unroll
            for (int i = 0; i < 8; i++) h[i] = __float2half(vy * AxP[48 + x + i]);
            *(uint4*)(row + e) = *reinterpret_cast<uint4*>(h);
        }
    }
    // A3: 12x12 + zero pad to 192 (scalar; tiny)
    {
        __half* row = g_A3 + (size_t)slot * 192;
        for (int j = t; j < 192; j += 128) {
            float v = 0.f;
            if (j < 144) v = norm * AyP[72 + j / 12] * AxP[72 + j % 12];
            row[j] = __float2half(v);
        }
    }
}

// ---------------- multi-level split-K fp16 GEMM ----------------
#define BM 64
#define BN 96
#define BK 64
#define A_BYTES (BM*BK*2)             // 8192
#define STB (A_BYTES + BN*BK*2)       // 20480 per stage
#define NSTAGE 4
#define SMEM_SZ (NSTAGE*STB + 1024)

__device__ __forceinline__ void cp16(uint32_t d, const void* s) {
    asm volatile("cp.async.cg.shared.global [%0], [%1], 16;\n" :: "r"(d), "l"(s));
}
__device__ __forceinline__ void ldm_x4(uint32_t &r0, uint32_t &r1, uint32_t &r2, uint32_t &r3, uint32_t addr) {
    asm volatile("ldmatrix.sync.aligned.m8n8.x4.shared.b16 {%0,%1,%2,%3}, [%4];\n"
                 : "=r"(r0),"=r"(r1),"=r"(r2),"=r"(r3) : "r"(addr));
}
__device__ __forceinline__ void ldm_x2(uint32_t &r0, uint32_t &r1, uint32_t addr) {
    asm volatile("ldmatrix.sync.aligned.m8n8.x2.shared.b16 {%0,%1}, [%2];\n"
                 : "=r"(r0),"=r"(r1) : "r"(addr));
}
__device__ __forceinline__ void mma16816(float* d, const uint32_t* a, const uint32_t* b) {
    asm volatile("mma.sync.aligned.m16n8k16.row.col.f32.f16.f16.f32 "
                 "{%0,%1,%2,%3}, {%4,%5,%6,%7}, {%8,%9}, {%0,%1,%2,%3};\n"
                 : "+f"(d[0]),"+f"(d[1]),"+f"(d[2]),"+f"(d[3])
                 : "r"(a[0]),"r"(a[1]),"r"(a[2]),"r"(a[3]),"r"(b[0]),"r"(b[1]));
}

__device__ __forceinline__ void load_stage(uint32_t sb, const __half* Ab, const __half* Bb,
                                           int rs, int bm0, int bn0, int kt, int slot, int tid) {
    uint32_t aS = sb + (uint32_t)slot * STB;
    uint32_t bS = aS + A_BYTES;
    int ch = tid & 7, r0 = tid >> 3;
    const __half* ap = Ab + (size_t)bm0 * rs + kt * BK + ch * 8;
    const __half* bp = Bb + (size_t)bn0 * rs + kt * BK + ch * 8;
    #pragma unroll
    for (int r = r0; r < BM; r += 32)
        cp16(aS + (r * 8 + (ch ^ (r & 7))) * 16, ap + (size_t)r * rs);
    #pragma unroll
    for (int r = r0; r < BN; r += 32)
        cp16(bS + (r * 8 + (ch ^ (r & 7))) * 16, bp + (size_t)r * rs);
}

// Flat CTA decode: [0,128) L0 (2n x 8m x 8sp), [128,256) L1 (4n x 8m x 4sp),
//                  [256,320) L2 (8n x 8m), [320,448) L3 (16n x 8m)
__global__ __launch_bounds__(256, 2) void k_gemm(float* __restrict__ out) {
    extern __shared__ __align__(1024) char smem_raw[];
    uint32_t sb = ((uint32_t)__cvta_generic_to_shared(smem_raw) + 1023) & ~1023u;
    const int tid = threadIdx.x, warp = tid >> 5, lane = tid & 31;
    const int wm = (warp >> 2) * 32;      // 2 M-warps
    const int wn = (warp & 3) * 24;       // 4 N-warps, warp tile 32x24

    int bx = blockIdx.x;
    int level, nt, mt, sp;
    if (bx < 128)      { level = 0; sp = bx & 7; int r = bx >> 3; nt = r & 1; mt = r >> 1; }
    else if (bx < 256) { level = 1; int l2 = bx - 128; sp = l2 & 3; int r = l2 >> 2; nt = r & 3; mt = r >> 2; }
    else if (bx < 320) { level = 2; int l2 = bx - 256; sp = 0; nt = l2 & 7;  mt = l2 >> 3; }
    else               { level = 3; int l2 = bx - 320; sp = 0; nt = l2 & 15; mt = l2 >> 4; }

    const __half *Ab, *Bb; int rs, noff, cs, ce;
    if (level == 0) {
        Ab = g_A0; Bb = g_F0; rs = 9216; noff = 0;
        int lo = g_ktlo[mt], nk0 = g_kthi[mt] - lo + 1;
        cs = lo + (nk0 * sp) / 8; ce = lo + (nk0 * (sp + 1)) / 8;
    } else if (level == 1) {
        Ab = g_A1; Bb = g_F1; rs = 2304; noff = 192; cs = 9 * sp; ce = 9 * sp + 9;
    } else if (level == 2) {
        Ab = g_A2; Bb = g_F2; rs = 576;  noff = 576; cs = 0; ce = 9;
    } else {
        Ab = g_A3; Bb = g_F3; rs = 192;  noff = 1344; cs = 0; ce = 3;
    }
    const int nk = ce - cs;
    if (nk <= 0) return;
    const int bm0 = mt * BM, bn0 = nt * BN;

    float acc[2][3][4];
    #pragma unroll
    for (int i = 0; i < 2; i++)
        #pragma unroll
        for (int j = 0; j < 3; j++)
            #pragma unroll
            for (int c = 0; c < 4; c++) acc[i][j][c] = 0.f;

    #pragma unroll
    for (int i = 0; i < 3; i++) {
        if (i < nk) {
            load_stage(sb, Ab, Bb, rs, bm0, bn0, cs + i, i, tid);
            asm volatile("cp.async.commit_group;" ::: "memory");
        }
    }

    for (int j = 0; j < nk; j++) {
        if (j <= nk - 3)      asm volatile("cp.async.wait_group 2;" ::: "memory");
        else if (j == nk - 2) asm volatile("cp.async.wait_group 1;" ::: "memory");
        else                  asm volatile("cp.async.wait_group 0;" ::: "memory");
        __syncthreads();
        if (j + 3 < nk) {
            load_stage(sb, Ab, Bb, rs, bm0, bn0, cs + j + 3, (j + 3) & 3, tid);
            asm volatile("cp.async.commit_group;" ::: "memory");
        }

        const uint32_t aS = sb + (uint32_t)(j & 3) * STB;
        const uint32_t bS = aS + A_BYTES;
        #pragma unroll
        for (int ks = 0; ks < 4; ks++) {
            uint32_t a[2][4];
            #pragma unroll
            for (int mf = 0; mf < 2; mf++) {
                int m  = wm + mf * 16 + (lane & 15);
                int kc = ks * 2 + (lane >> 4);
                ldm_x4(a[mf][0], a[mf][1], a[mf][2], a[mf][3],
                       aS + (m * 8 + (kc ^ (m & 7))) * 16);
            }
            uint32_t b[3][2];
            {
                int g = lane >> 3;
                int n  = wn + (g >> 1) * 8 + (lane & 7);
                int kc = ks * 2 + (g & 1);
                ldm_x4(b[0][0], b[0][1], b[1][0], b[1][1],
                       bS + (n * 8 + (kc ^ (n & 7))) * 16);
            }
            {
                int g = lane >> 3;
                int n  = wn + 16 + (lane & 7);
                int kc = ks * 2 + (g & 1);
                ldm_x2(b[2][0], b[2][1], bS + (n * 8 + (kc ^ (n & 7))) * 16);
            }
            #pragma unroll
            for (int mf = 0; mf < 2; mf++)
                #pragma unroll
                for (int nf = 0; nf < 3; nf++)
                    mma16816(acc[mf][nf], a[mf], b[nf]);
        }
    }

    // Epilogue: scatter rows through perm; split-K levels accumulate atomically.
    int r0 = lane >> 2, c0 = (lane & 3) * 2;
    #pragma unroll
    for (int mf = 0; mf < 2; mf++) {
        int mA = bm0 + wm + mf * 16 + r0;
        int rowA = g_perm[mA];
        int rowB = g_perm[mA + 8];
        #pragma unroll
        for (int nf = 0; nf < 3; nf++) {
            int n = noff + bn0 + wn + nf * 8 + c0;
            float* p0 = &out[(size_t)rowA * CTOT + n];
            float* p1 = &out[(size_t)rowB * CTOT + n];
            if (level <= 1) {
                atomicAdd(p0,     acc[mf][nf][0]);
                atomicAdd(p0 + 1, acc[mf][nf][1]);
                atomicAdd(p1,     acc[mf][nf][2]);
                atomicAdd(p1 + 1, acc[mf][nf][3]);
            } else {
                *(float2*)p0 = make_float2(acc[mf][nf][0], acc[mf][nf][1]);
                *(float2*)p1 = make_float2(acc[mf][nf][2], acc[mf][nf][3]);
            }
        }
    }
}

extern "C" void kernel_launch(void* const* d_in, const int* in_sizes, int n_in,
                              void* d_out, int out_size) {
    const float* feat0 = (const float*)d_in[0];
    const float* feat1 = (const float*)d_in[1];
    const float* feat2 = (const float*)d_in[2];
    const float* feat3 = (const float*)d_in[3];
    const float* boxes = (const float*)d_in[4];
    float* out = (float*)d_out;

    cudaFuncSetAttribute(k_gemm, cudaFuncAttributeMaxDynamicSharedMemorySize, SMEM_SZ);

    k_zero576<<<288, 256>>>((float4*)out);        // zero split-K stripe (cols < 576)
    k_cvt<0><<<864, 256>>>((const float4*)feat0);
    k_cvt<1><<<432, 256>>>((const float4*)feat1);
    k_cvt<2><<<216, 256>>>((const float4*)feat2);
    k_cvt3<<<1536, 192>>>(feat3);
    k_boxprep<<<1, 512>>>(boxes);
    k_weights<<<NBOX, 128>>>(boxes);
    k_gemm<<<448, 256, SMEM_SZ>>>(out);
}

// round 8
// speedup vs baseline: 4.7168x; 1.0931x over previous
#include <cuda_runtime.h>
#include <cuda_fp16.h>
#include <cstdint>

#define CTOT 2880
#define NBOX 512

// Raw features in fp16, K-major per level (natural [C][pixel] layout).
__device__ __align__(256) __half g_F0[192 * 9216];
__device__ __align__(256) __half g_F1[384 * 2304];
__device__ __align__(256) __half g_F2[768 * 576];
__device__ __align__(256) __half g_F3[1536 * 192];   // 144 + 48 zero pad
// Projected ROI weight rows per level (sorted box order).
__device__ __align__(256) __half g_A0[NBOX * 9216];
__device__ __align__(256) __half g_A1[NBOX * 2304];
__device__ __align__(256) __half g_A2[NBOX * 576];
__device__ __align__(256) __half g_A3[NBOX * 192];
__device__ int g_perm[NBOX];          // sorted slot -> original box index
__device__ int g_ktlo[8], g_kthi[8];  // per 64-box M-tile: level-0 K-chunk range

// ---------------- fused prep: converts + pad + out-stripe zero + boxprep ----------------
// Block ranges: [0,864) cvt0, [864,1296) cvt1, [1296,1512) cvt2, [1512,1620) cvt3 data,
// [1620,1656) cvt3 pad, [1656,1944) zero out[:, 0:576), block 1944 = boxprep.
__device__ __forceinline__ uint4 pack8(float4 a, float4 b) {
    __half2 h[4];
    h[0] = __floats2half2_rn(a.x, a.y);
    h[1] = __floats2half2_rn(a.z, a.w);
    h[2] = __floats2half2_rn(b.x, b.y);
    h[3] = __floats2half2_rn(b.z, b.w);
    return *reinterpret_cast<uint4*>(h);
}

__global__ __launch_bounds__(256) void k_prep(
    const float4* __restrict__ f0, const float4* __restrict__ f1,
    const float4* __restrict__ f2, const float*  __restrict__ f3,
    const float*  __restrict__ boxes, float4* __restrict__ out4)
{
    int b = blockIdx.x, t = threadIdx.x;
    if (b < 864) {
        int i = b * 256 + t;
        reinterpret_cast<uint4*>(g_F0)[i] = pack8(f0[2*i], f0[2*i+1]);
    } else if (b < 1296) {
        int i = (b - 864) * 256 + t;
        reinterpret_cast<uint4*>(g_F1)[i] = pack8(f1[2*i], f1[2*i+1]);
    } else if (b < 1512) {
        int i = (b - 1296) * 256 + t;
        reinterpret_cast<uint4*>(g_F2)[i] = pack8(f2[2*i], f2[2*i+1]);
    } else if (b < 1620) {
        int i = (b - 1512) * 256 + t;          // 27648: 1536 rows x 18 groups
        int c = i / 18, j = i - c * 18;
        const float4* s4 = reinterpret_cast<const float4*>(f3) + c * 36 + j * 2;
        reinterpret_cast<uint4*>(g_F3)[c * 24 + j] = pack8(s4[0], s4[1]);
    } else if (b < 1656) {
        int i = (b - 1620) * 256 + t;          // 9216: 1536 rows x 6 pad groups
        int c = i / 6, j = i - c * 6;
        reinterpret_cast<uint4*>(g_F3)[c * 24 + 18 + j] = make_uint4(0, 0, 0, 0);
    } else if (b < 1944) {
        int i = (b - 1656) * 256 + t;          // 73728: 512 rows x 144 float4
        int k = i / 144, c4 = i - k * 144;
        out4[k * 720 + c4] = make_float4(0.f, 0.f, 0.f, 0.f);
    } else {
        // ---- boxprep: touched-y range, counting sort by y-center, tile K ranges ----
        __shared__ int hist[256], offs[256];
        __shared__ int tlo[8], thi[8];
        hist[t] = 0;
        if (t < 8) { tlo[t] = 1 << 30; thi[t] = -1; }
        __syncthreads();
        int lo[2], hi[2], key[2];
        #pragma unroll
        for (int q = 0; q < 2; q++) {
            int bx = t + q * 256;
            float y1 = boxes[bx * 4 + 1], y2 = boxes[bx * 4 + 3];
            float rh = fmaxf(y2 - y1, 1.f);
            float gh = fminf(fmaxf(ceilf(rh / 7.f), 1.f), 8.f);
            float bb = rh / 7.f;
            int ymin = 95, ymax = 0;
            #pragma unroll
            for (int pp = 0; pp < 7; pp++)
                #pragma unroll
                for (int ss = 0; ss < 8; ss++) {
                    if ((float)ss < gh) {
                        float coord = y1 + (float)pp * bb + ((float)ss + 0.5f) * (bb / gh);
                        if (!(coord < -1.f || coord > 96.f)) {
                            float c = fmaxf(coord, 0.f);
                            int i0 = (int)floorf(c);
                            int i1 = (i0 >= 95) ? 95 : i0 + 1;
                            if (i0 > 95) i0 = 95;
                            ymin = min(ymin, i0);
                            ymax = max(ymax, i1);
                        }
                    }
                }
            lo[q] = (ymin * 96) / 64;
            hi[q] = (ymax * 96 + 95) / 64;
            key[q] = ymin + ymax;
            atomicAdd(&hist[key[q]], 1);
        }
        __syncthreads();
        if (t == 0) { int acc = 0; for (int i = 0; i < 256; i++) { offs[i] = acc; acc += hist[i]; } }
        __syncthreads();
        #pragma unroll
        for (int q = 0; q < 2; q++) {
            int pos = atomicAdd(&offs[key[q]], 1);
            g_perm[pos] = t + q * 256;
            atomicMin(&tlo[pos >> 6], lo[q]);
            atomicMax(&thi[pos >> 6], hi[q]);
        }
        __syncthreads();
        if (t < 8) { g_ktlo[t] = tlo[t]; g_kthi[t] = thi[t]; }
    }
}

// ---------------- per-box weights: build Ax/Ay, project through upsample, write A0..A3 ----
__global__ void k_weights(const float* __restrict__ boxes) {
    __shared__ float Ax[96], Ay[96];
    __shared__ float AxP[84], AyP[84];   // [0,48) L1, [48,72) L2, [72,84) L3
    __shared__ float s_norm;
    int slot = blockIdx.x;
    int k = g_perm[slot];
    int t = threadIdx.x;  // 128 threads
    if (t < 96) { Ax[t] = 0.f; Ay[t] = 0.f; }
    if (t < 84) { AxP[t] = 0.f; AyP[t] = 0.f; }
    float x1 = boxes[k*4+0], y1 = boxes[k*4+1];
    float x2 = boxes[k*4+2], y2 = boxes[k*4+3];
    float rw = fmaxf(x2 - x1, 1.0f), rh = fmaxf(y2 - y1, 1.0f);
    float gw = fminf(fmaxf(ceilf(rw / 7.0f), 1.0f), 8.0f);
    float gh = fminf(fmaxf(ceilf(rh / 7.0f), 1.0f), 8.0f);
    if (t == 0) s_norm = 1.0f / (gh * gw * 49.0f);
    __syncthreads();
    if (t < 112) {
        int isY = t >= 56;
        int i = isY ? t - 56 : t;
        int pp = i >> 3, ss = i & 7;
        float lo = isY ? y1 : x1;
        float sz = isY ? rh : rw;
        float g  = isY ? gh : gw;
        float* Aarr = isY ? Ay : Ax;
        if ((float)ss < g) {
            float b = sz / 7.0f;
            float coord = lo + (float)pp * b + ((float)ss + 0.5f) * (b / g);
            if (!(coord < -1.0f || coord > 96.0f)) {
                float c = fmaxf(coord, 0.0f);
                int i0 = (int)floorf(c);
                int i1; float f;
                if (i0 >= 95) { i0 = 95; i1 = 95; f = 0.f; }
                else          { i1 = i0 + 1; f = c - (float)i0; }
                atomicAdd(&Aarr[i0], 1.0f - f);
                atomicAdd(&Aarr[i1], f);
            }
        }
    }
    __syncthreads();
    // Project through the bilinear upsample: A_l = U_l^T A (separable, per axis).
    if (t < 96) {
        float axv = Ax[t], ayv = Ay[t];
        auto proj = [&](float* dst, float v, int HS, float sc) {
            float Xf = ((float)t + 0.5f) * sc - 0.5f;
            float Xc = fminf(fmaxf(Xf, 0.f), (float)(HS - 1));
            int x0 = min((int)Xc, HS - 2);
            float f = Xc - (float)x0;
            atomicAdd(dst + x0, v * (1.f - f));
            atomicAdd(dst + x0 + 1, v * f);
        };
        proj(AxP + 0,  axv, 48, 0.5f);   proj(AyP + 0,  ayv, 48, 0.5f);
        proj(AxP + 48, axv, 24, 0.25f);  proj(AyP + 48, ayv, 24, 0.25f);
        proj(AxP + 72, axv, 12, 0.125f); proj(AyP + 72, ayv, 12, 0.125f);
    }
    __syncthreads();
    float norm = s_norm;
    // A0: write only this tile's K-chunk union (all the GEMM ever reads).
    {
        int plo = g_ktlo[slot >> 6] * 64;
        int phi = (g_kthi[slot >> 6] + 1) * 64;
        __half* row = g_A0 + (size_t)slot * 9216;
        for (int e = plo + t * 8; e < phi; e += 128 * 8) {
            int y = e / 96, x = e - y * 96;
            float vy = norm * Ay[y];
            __align__(16) __half h[8];
            #pragma unroll
            for (int i = 0; i < 8; i++) h[i] = __float2half(vy * Ax[x + i]);
            *(uint4*)(row + e) = *reinterpret_cast<uint4*>(h);
        }
    }
    // A1: 48x48
    {
        __half* row = g_A1 + (size_t)slot * 2304;
        for (int e = t * 8; e < 2304; e += 128 * 8) {
            int y = e / 48, x = e - y * 48;
            float vy = norm * AyP[y];
            __align__(16) __half h[8];
            #pragma unroll
            for (int i = 0; i < 8; i++) h[i] = __float2half(vy * AxP[x + i]);
            *(uint4*)(row + e) = *reinterpret_cast<uint4*>(h);
        }
    }
    // A2: 24x24
    {
        __half* row = g_A2 + (size_t)slot * 576;
        for (int e = t * 8; e < 576; e += 128 * 8) {
            int y = e / 24, x = e - y * 24;
            float vy = norm * AyP[48 + y];
            __align__(16) __half h[8];
            #pragma unroll
            for (int i = 0; i < 8; i++) h[i] = __float2half(vy * AxP[48 + x + i]);
            *(uint4*)(row + e) = *reinterpret_cast<uint4*>(h);
        }
    }
    // A3: 12x12 + zero pad to 192 (scalar; tiny)
    {
        __half* row = g_A3 + (size_t)slot * 192;
        for (int j = t; j < 192; j += 128) {
            float v = 0.f;
            if (j < 144) v = norm * AyP[72 + j / 12] * AxP[72 + j % 12];
            row[j] = __float2half(v);
        }
    }
}

// ---------------- multi-level split-K fp16 GEMM ----------------
#define BM 64
#define BN 96
#define BK 64
#define A_BYTES (BM*BK*2)             // 8192
#define STB (A_BYTES + BN*BK*2)       // 20480 per stage
#define NSTAGE 4
#define SMEM_SZ (NSTAGE*STB + 1024)

__device__ __forceinline__ void cp16(uint32_t d, const void* s) {
    asm volatile("cp.async.cg.shared.global [%0], [%1], 16;\n" :: "r"(d), "l"(s));
}
__device__ __forceinline__ void ldm_x4(uint32_t &r0, uint32_t &r1, uint32_t &r2, uint32_t &r3, uint32_t addr) {
    asm volatile("ldmatrix.sync.aligned.m8n8.x4.shared.b16 {%0,%1,%2,%3}, [%4];\n"
                 : "=r"(r0),"=r"(r1),"=r"(r2),"=r"(r3) : "r"(addr));
}
__device__ __forceinline__ void ldm_x2(uint32_t &r0, uint32_t &r1, uint32_t addr) {
    asm volatile("ldmatrix.sync.aligned.m8n8.x2.shared.b16 {%0,%1}, [%2];\n"
                 : "=r"(r0),"=r"(r1) : "r"(addr));
}
__device__ __forceinline__ void mma16816(float* d, const uint32_t* a, const uint32_t* b) {
    asm volatile("mma.sync.aligned.m16n8k16.row.col.f32.f16.f16.f32 "
                 "{%0,%1,%2,%3}, {%4,%5,%6,%7}, {%8,%9}, {%0,%1,%2,%3};\n"
                 : "+f"(d[0]),"+f"(d[1]),"+f"(d[2]),"+f"(d[3])
                 : "r"(a[0]),"r"(a[1]),"r"(a[2]),"r"(a[3]),"r"(b[0]),"r"(b[1]));
}

__device__ __forceinline__ void load_stage(uint32_t sb, const __half* Ab, const __half* Bb,
                                           int rs, int bm0, int bn0, int kt, int slot, int tid) {
    uint32_t aS = sb + (uint32_t)slot * STB;
    uint32_t bS = aS + A_BYTES;
    int ch = tid & 7, r0 = tid >> 3;
    const __half* ap = Ab + (size_t)bm0 * rs + kt * BK + ch * 8;
    const __half* bp = Bb + (size_t)bn0 * rs + kt * BK + ch * 8;
    #pragma unroll
    for (int r = r0; r < BM; r += 32)
        cp16(aS + (r * 8 + (ch ^ (r & 7))) * 16, ap + (size_t)r * rs);
    #pragma unroll
    for (int r = r0; r < BN; r += 32)
        cp16(bS + (r * 8 + (ch ^ (r & 7))) * 16, bp + (size_t)r * rs);
}

// Flat CTA decode: [0,128) L0 (2n x 8m x 8sp), [128,256) L1 (4n x 8m x 4sp),
//                  [256,320) L2 (8n x 8m), [320,448) L3 (16n x 8m)
__global__ __launch_bounds__(256, 2) void k_gemm(float* __restrict__ out) {
    extern __shared__ __align__(1024) char smem_raw[];
    uint32_t sb = ((uint32_t)__cvta_generic_to_shared(smem_raw) + 1023) & ~1023u;
    const int tid = threadIdx.x, warp = tid >> 5, lane = tid & 31;
    const int wm = (warp >> 2) * 32;      // 2 M-warps
    const int wn = (warp & 3) * 24;       // 4 N-warps, warp tile 32x24

    int bx = blockIdx.x;
    int level, nt, mt, sp;
    if (bx < 128)      { level = 0; sp = bx & 7; int r = bx >> 3; nt = r & 1; mt = r >> 1; }
    else if (bx < 256) { level = 1; int l2 = bx - 128; sp = l2 & 3; int r = l2 >> 2; nt = r & 3; mt = r >> 2; }
    else if (bx < 320) { level = 2; int l2 = bx - 256; sp = 0; nt = l2 & 7;  mt = l2 >> 3; }
    else               { level = 3; int l2 = bx - 320; sp = 0; nt = l2 & 15; mt = l2 >> 4; }

    const __half *Ab, *Bb; int rs, noff, cs, ce;
    if (level == 0) {
        Ab = g_A0; Bb = g_F0; rs = 9216; noff = 0;
        int lo = g_ktlo[mt], nk0 = g_kthi[mt] - lo + 1;
        cs = lo + (nk0 * sp) / 8; ce = lo + (nk0 * (sp + 1)) / 8;
    } else if (level == 1) {
        Ab = g_A1; Bb = g_F1; rs = 2304; noff = 192; cs = 9 * sp; ce = 9 * sp + 9;
    } else if (level == 2) {
        Ab = g_A2; Bb = g_F2; rs = 576;  noff = 576; cs = 0; ce = 9;
    } else {
        Ab = g_A3; Bb = g_F3; rs = 192;  noff = 1344; cs = 0; ce = 3;
    }
    const int nk = ce - cs;
    if (nk <= 0) return;
    const int bm0 = mt * BM, bn0 = nt * BN;

    float acc[2][3][4];
    #pragma unroll
    for (int i = 0; i < 2; i++)
        #pragma unroll
        for (int j = 0; j < 3; j++)
            #pragma unroll
            for (int c = 0; c < 4; c++) acc[i][j][c] = 0.f;

    #pragma unroll
    for (int i = 0; i < 3; i++) {
        if (i < nk) {
            load_stage(sb, Ab, Bb, rs, bm0, bn0, cs + i, i, tid);
            asm volatile("cp.async.commit_group;" ::: "memory");
        }
    }

    for (int j = 0; j < nk; j++) {
        if (j <= nk - 3)      asm volatile("cp.async.wait_group 2;" ::: "memory");
        else if (j == nk - 2) asm volatile("cp.async.wait_group 1;" ::: "memory");
        else                  asm volatile("cp.async.wait_group 0;" ::: "memory");
        __syncthreads();
        if (j + 3 < nk) {
            load_stage(sb, Ab, Bb, rs, bm0, bn0, cs + j + 3, (j + 3) & 3, tid);
            asm volatile("cp.async.commit_group;" ::: "memory");
        }

        const uint32_t aS = sb + (uint32_t)(j & 3) * STB;
        const uint32_t bS = aS + A_BYTES;
        #pragma unroll
        for (int ks = 0; ks < 4; ks++) {
            uint32_t a[2][4];
            #pragma unroll
            for (int mf = 0; mf < 2; mf++) {
                int m  = wm + mf * 16 + (lane & 15);
                int kc = ks * 2 + (lane >> 4);
                ldm_x4(a[mf][0], a[mf][1], a[mf][2], a[mf][3],
                       aS + (m * 8 + (kc ^ (m & 7))) * 16);
            }
            uint32_t b[3][2];
            {
                int g = lane >> 3;
                int n  = wn + (g >> 1) * 8 + (lane & 7);
                int kc = ks * 2 + (g & 1);
                ldm_x4(b[0][0], b[0][1], b[1][0], b[1][1],
                       bS + (n * 8 + (kc ^ (n & 7))) * 16);
            }
            {
                int g = lane >> 3;
                int n  = wn + 16 + (lane & 7);
                int kc = ks * 2 + (g & 1);
                ldm_x2(b[2][0], b[2][1], bS + (n * 8 + (kc ^ (n & 7))) * 16);
            }
            #pragma unroll
            for (int mf = 0; mf < 2; mf++)
                #pragma unroll
                for (int nf = 0; nf < 3; nf++)
                    mma16816(acc[mf][nf], a[mf], b[nf]);
        }
    }

    // Epilogue: scatter rows through perm; split-K levels accumulate atomically.
    int r0 = lane >> 2, c0 = (lane & 3) * 2;
    #pragma unroll
    for (int mf = 0; mf < 2; mf++) {
        int mA = bm0 + wm + mf * 16 + r0;
        int rowA = g_perm[mA];
        int rowB = g_perm[mA + 8];
        #pragma unroll
        for (int nf = 0; nf < 3; nf++) {
            int n = noff + bn0 + wn + nf * 8 + c0;
            float* p0 = &out[(size_t)rowA * CTOT + n];
            float* p1 = &out[(size_t)rowB * CTOT + n];
            if (level <= 1) {
                atomicAdd(p0,     acc[mf][nf][0]);
                atomicAdd(p0 + 1, acc[mf][nf][1]);
                atomicAdd(p1,     acc[mf][nf][2]);
                atomicAdd(p1 + 1, acc[mf][nf][3]);
            } else {
                *(float2*)p0 = make_float2(acc[mf][nf][0], acc[mf][nf][1]);
                *(float2*)p1 = make_float2(acc[mf][nf][2], acc[mf][nf][3]);
            }
        }
    }
}

extern "C" void kernel_launch(void* const* d_in, const int* in_sizes, int n_in,
                              void* d_out, int out_size) {
    const float* feat0 = (const float*)d_in[0];
    const float* feat1 = (const float*)d_in[1];
    const float* feat2 = (const float*)d_in[2];
    const float* feat3 = (const float*)d_in[3];
    const float* boxes = (const float*)d_in[4];
    float* out = (float*)d_out;

    cudaFuncSetAttribute(k_gemm, cudaFuncAttributeMaxDynamicSharedMemorySize, SMEM_SZ);

    k_prep<<<1945, 256>>>((const float4*)feat0, (const float4*)feat1,
                          (const float4*)feat2, feat3, boxes, (float4*)out);
    k_weights<<<NBOX, 128>>>(boxes);
    k_gemm<<<448, 256, SMEM_SZ>>>(out);
}

// round 9
// speedup vs baseline: 5.2778x; 1.1189x over previous
#include <cuda_runtime.h>
#include <cuda_fp16.h>
#include <cstdint>

#define CTOT 2880
#define NBOX 512

// Raw features in fp16, K-major per level (natural [C][pixel] layout).
__device__ __align__(256) __half g_F0[192 * 9216];
__device__ __align__(256) __half g_F1[384 * 2304];
__device__ __align__(256) __half g_F2[768 * 576];
__device__ __align__(256) __half g_F3[1536 * 192];   // 144 + 48 zero pad
// Projected ROI weight rows per level (sorted box order).
__device__ __align__(256) __half g_A0[NBOX * 9216];
__device__ __align__(256) __half g_A1[NBOX * 2304];
__device__ __align__(256) __half g_A2[NBOX * 576];
__device__ __align__(256) __half g_A3[NBOX * 192];
__device__ int g_perm[NBOX];          // sorted slot -> original box index
__device__ int g_ktlo[8], g_kthi[8];  // per 64-box M-tile: level-0 K-chunk range

// ---------------- fused prep: boxprep (block 0) + converts + pad + out-stripe zero ----------
// Block ranges: 0 boxprep, [1,217) cvt0, [217,325) cvt1, [325,379) cvt2,
// [379,406) cvt3 data, [406,415) cvt3 pad, [415,487) zero out[:, 0:576).
// Convert blocks: 4 uint4 per thread (MLP 8), coalesced t + k*256 pattern.
__device__ __forceinline__ uint4 pack8(float4 a, float4 b) {
    __half2 h[4];
    h[0] = __floats2half2_rn(a.x, a.y);
    h[1] = __floats2half2_rn(a.z, a.w);
    h[2] = __floats2half2_rn(b.x, b.y);
    h[3] = __floats2half2_rn(b.z, b.w);
    return *reinterpret_cast<uint4*>(h);
}

__global__ __launch_bounds__(256) void k_prep(
    const float4* __restrict__ f0, const float4* __restrict__ f1,
    const float4* __restrict__ f2, const float*  __restrict__ f3,
    const float*  __restrict__ boxes, float4* __restrict__ out4)
{
    int b = blockIdx.x, t = threadIdx.x;
    if (b == 0) {
        // ---- boxprep: touched-y range, counting sort by y-center, tile K ranges ----
        __shared__ int hist[256], offs[256];
        __shared__ int tlo[8], thi[8];
        __shared__ int wsum[8];
        hist[t] = 0;
        if (t < 8) { tlo[t] = 1 << 30; thi[t] = -1; }
        __syncthreads();
        int lo[2], hi[2], key[2];
        #pragma unroll
        for (int q = 0; q < 2; q++) {
            int bx = t + q * 256;
            float y1 = boxes[bx * 4 + 1], y2 = boxes[bx * 4 + 3];
            float rh = fmaxf(y2 - y1, 1.f);
            float gh = fminf(fmaxf(ceilf(rh / 7.f), 1.f), 8.f);
            float bb = rh / 7.f;
            int ymin = 95, ymax = 0;
            #pragma unroll
            for (int pp = 0; pp < 7; pp++)
                #pragma unroll
                for (int ss = 0; ss < 8; ss++) {
                    if ((float)ss < gh) {
                        float coord = y1 + (float)pp * bb + ((float)ss + 0.5f) * (bb / gh);
                        if (!(coord < -1.f || coord > 96.f)) {
                            float c = fmaxf(coord, 0.f);
                            int i0 = (int)floorf(c);
                            int i1 = (i0 >= 95) ? 95 : i0 + 1;
                            if (i0 > 95) i0 = 95;
                            ymin = min(ymin, i0);
                            ymax = max(ymax, i1);
                        }
                    }
                }
            lo[q] = (ymin * 96) / 64;
            hi[q] = (ymax * 96 + 95) / 64;
            key[q] = ymin + ymax;
            atomicAdd(&hist[key[q]], 1);
        }
        __syncthreads();
        // Parallel exclusive prefix scan over 256 bins (warp shuffles + warp-sum scan).
        {
            int h = hist[t];
            int v = h;
            #pragma unroll
            for (int d = 1; d < 32; d <<= 1) {
                int n = __shfl_up_sync(0xFFFFFFFFu, v, d);
                if ((t & 31) >= d) v += n;
            }
            if ((t & 31) == 31) wsum[t >> 5] = v;
            __syncthreads();
            if (t < 8) {
                int w = wsum[t];
                #pragma unroll
                for (int d = 1; d < 8; d <<= 1) {
                    int n = __shfl_up_sync(0xFFu, w, d);
                    if (t >= d) w += n;
                }
                wsum[t] = w;
            }
            __syncthreads();
            int excl = v - h + ((t >= 32) ? wsum[(t >> 5) - 1] : 0);
            offs[t] = excl;
        }
        __syncthreads();
        #pragma unroll
        for (int q = 0; q < 2; q++) {
            int pos = atomicAdd(&offs[key[q]], 1);
            g_perm[pos] = t + q * 256;
            atomicMin(&tlo[pos >> 6], lo[q]);
            atomicMax(&thi[pos >> 6], hi[q]);
        }
        __syncthreads();
        if (t < 8) { g_ktlo[t] = tlo[t]; g_kthi[t] = thi[t]; }
    } else if (b < 217) {
        int i0 = (b - 1) * 1024 + t;
        uint4* dst = reinterpret_cast<uint4*>(g_F0);
        float4 a[4], c[4];
        #pragma unroll
        for (int k = 0; k < 4; k++) { int i = i0 + k * 256; a[k] = f0[2*i]; c[k] = f0[2*i+1]; }
        #pragma unroll
        for (int k = 0; k < 4; k++) dst[i0 + k * 256] = pack8(a[k], c[k]);
    } else if (b < 325) {
        int i0 = (b - 217) * 1024 + t;
        uint4* dst = reinterpret_cast<uint4*>(g_F1);
        float4 a[4], c[4];
        #pragma unroll
        for (int k = 0; k < 4; k++) { int i = i0 + k * 256; a[k] = f1[2*i]; c[k] = f1[2*i+1]; }
        #pragma unroll
        for (int k = 0; k < 4; k++) dst[i0 + k * 256] = pack8(a[k], c[k]);
    } else if (b < 379) {
        int i0 = (b - 325) * 1024 + t;
        uint4* dst = reinterpret_cast<uint4*>(g_F2);
        float4 a[4], c[4];
        #pragma unroll
        for (int k = 0; k < 4; k++) { int i = i0 + k * 256; a[k] = f2[2*i]; c[k] = f2[2*i+1]; }
        #pragma unroll
        for (int k = 0; k < 4; k++) dst[i0 + k * 256] = pack8(a[k], c[k]);
    } else if (b < 406) {
        int i0 = (b - 379) * 1024 + t;          // 27648 groups: 1536 rows x 18
        const float4* s4 = reinterpret_cast<const float4*>(f3);
        float4 a[4], c[4];
        int ci[4], ji[4];
        #pragma unroll
        for (int k = 0; k < 4; k++) {
            int i = i0 + k * 256;
            ci[k] = i / 18; ji[k] = i - ci[k] * 18;
            a[k] = s4[ci[k] * 36 + ji[k] * 2];
            c[k] = s4[ci[k] * 36 + ji[k] * 2 + 1];
        }
        #pragma unroll
        for (int k = 0; k < 4; k++)
            reinterpret_cast<uint4*>(g_F3)[ci[k] * 24 + ji[k]] = pack8(a[k], c[k]);
    } else if (b < 415) {
        int i0 = (b - 406) * 1024 + t;          // 9216 pad groups: 1536 rows x 6
        #pragma unroll
        for (int k = 0; k < 4; k++) {
            int i = i0 + k * 256;
            int c = i / 6, j = i - c * 6;
            reinterpret_cast<uint4*>(g_F3)[c * 24 + 18 + j] = make_uint4(0, 0, 0, 0);
        }
    } else {
        int i0 = (b - 415) * 1024 + t;          // 73728: 512 rows x 144 float4
        #pragma unroll
        for (int k = 0; k < 4; k++) {
            int i = i0 + k * 256;
            int kk = i / 144, c4 = i - kk * 144;
            out4[kk * 720 + c4] = make_float4(0.f, 0.f, 0.f, 0.f);
        }
    }
}

// ---------------- per-box weights: build Ax/Ay, project through upsample, write A0..A3 ----
__global__ void k_weights(const float* __restrict__ boxes) {
    __shared__ float Ax[96], Ay[96];
    __shared__ float AxP[84], AyP[84];   // [0,48) L1, [48,72) L2, [72,84) L3
    __shared__ float s_norm;
    int slot = blockIdx.x;
    int k = g_perm[slot];
    int t = threadIdx.x;  // 128 threads
    if (t < 96) { Ax[t] = 0.f; Ay[t] = 0.f; }
    if (t < 84) { AxP[t] = 0.f; AyP[t] = 0.f; }
    float x1 = boxes[k*4+0], y1 = boxes[k*4+1];
    float x2 = boxes[k*4+2], y2 = boxes[k*4+3];
    float rw = fmaxf(x2 - x1, 1.0f), rh = fmaxf(y2 - y1, 1.0f);
    float gw = fminf(fmaxf(ceilf(rw / 7.0f), 1.0f), 8.0f);
    float gh = fminf(fmaxf(ceilf(rh / 7.0f), 1.0f), 8.0f);
    if (t == 0) s_norm = 1.0f / (gh * gw * 49.0f);
    __syncthreads();
    if (t < 112) {
        int isY = t >= 56;
        int i = isY ? t - 56 : t;
        int pp = i >> 3, ss = i & 7;
        float lo = isY ? y1 : x1;
        float sz = isY ? rh : rw;
        float g  = isY ? gh : gw;
        float* Aarr = isY ? Ay : Ax;
        if ((float)ss < g) {
            float b = sz / 7.0f;
            float coord = lo + (float)pp * b + ((float)ss + 0.5f) * (b / g);
            if (!(coord < -1.0f || coord > 96.0f)) {
                float c = fmaxf(coord, 0.0f);
                int i0 = (int)floorf(c);
                int i1; float f;
                if (i0 >= 95) { i0 = 95; i1 = 95; f = 0.f; }
                else          { i1 = i0 + 1; f = c - (float)i0; }
                atomicAdd(&Aarr[i0], 1.0f - f);
                atomicAdd(&Aarr[i1], f);
            }
        }
    }
    __syncthreads();
    // Project through the bilinear upsample: A_l = U_l^T A (separable, per axis).
    if (t < 96) {
        float axv = Ax[t], ayv = Ay[t];
        auto proj = [&](float* dst, float v, int HS, float sc) {
            float Xf = ((float)t + 0.5f) * sc - 0.5f;
            float Xc = fminf(fmaxf(Xf, 0.f), (float)(HS - 1));
            int x0 = min((int)Xc, HS - 2);
            float f = Xc - (float)x0;
            atomicAdd(dst + x0, v * (1.f - f));
            atomicAdd(dst + x0 + 1, v * f);
        };
        proj(AxP + 0,  axv, 48, 0.5f);   proj(AyP + 0,  ayv, 48, 0.5f);
        proj(AxP + 48, axv, 24, 0.25f);  proj(AyP + 48, ayv, 24, 0.25f);
        proj(AxP + 72, axv, 12, 0.125f); proj(AyP + 72, ayv, 12, 0.125f);
    }
    __syncthreads();
    float norm = s_norm;
    // A0: write only this tile's K-chunk union (all the GEMM ever reads).
    {
        int plo = g_ktlo[slot >> 6] * 64;
        int phi = (g_kthi[slot >> 6] + 1) * 64;
        __half* row = g_A0 + (size_t)slot * 9216;
        for (int e = plo + t * 8; e < phi; e += 128 * 8) {
            int y = e / 96, x = e - y * 96;
            float vy = norm * Ay[y];
            __align__(16) __half h[8];
            #pragma unroll
            for (int i = 0; i < 8; i++) h[i] = __float2half(vy * Ax[x + i]);
            *(uint4*)(row + e) = *reinterpret_cast<uint4*>(h);
        }
    }
    // A1: 48x48
    {
        __half* row = g_A1 + (size_t)slot * 2304;
        for (int e = t * 8; e < 2304; e += 128 * 8) {
            int y = e / 48, x = e - y * 48;
            float vy = norm * AyP[y];
            __align__(16) __half h[8];
            #pragma unroll
            for (int i = 0; i < 8; i++) h[i] = __float2half(vy * AxP[x + i]);
            *(uint4*)(row + e) = *reinterpret_cast<uint4*>(h);
        }
    }
    // A2: 24x24
    {
        __half* row = g_A2 + (size_t)slot * 576;
        for (int e = t * 8; e < 576; e += 128 * 8) {
            int y = e / 24, x = e - y * 24;
            float vy = norm * AyP[48 + y];
            __align__(16) __half h[8];
            #pragma unroll
            for (int i = 0; i < 8; i++) h[i] = __float2half(vy * AxP[48 + x + i]);
            *(uint4*)(row + e) = *reinterpret_cast<uint4*>(h);
        }
    }
    // A3: 12x12 + zero pad to 192 (scalar; tiny)
    {
        __half* row = g_A3 + (size_t)slot * 192;
        for (int j = t; j < 192; j += 128) {
            float v = 0.f;
            if (j < 144) v = norm * AyP[72 + j / 12] * AxP[72 + j % 12];
            row[j] = __float2half(v);
        }
    }
}

// ---------------- multi-level split-K fp16 GEMM ----------------
#define BM 64
#define BN 96
#define BK 64
#define A_BYTES (BM*BK*2)             // 8192
#define STB (A_BYTES + BN*BK*2)       // 20480 per stage
#define NSTAGE 4
#define SMEM_SZ (NSTAGE*STB + 1024)

__device__ __forceinline__ void cp16(uint32_t d, const void* s) {
    asm volatile("cp.async.cg.shared.global [%0], [%1], 16;\n" :: "r"(d), "l"(s));
}
__device__ __forceinline__ void ldm_x4(uint32_t &r0, uint32_t &r1, uint32_t &r2, uint32_t &r3, uint32_t addr) {
    asm volatile("ldmatrix.sync.aligned.m8n8.x4.shared.b16 {%0,%1,%2,%3}, [%4];\n"
                 : "=r"(r0),"=r"(r1),"=r"(r2),"=r"(r3) : "r"(addr));
}
__device__ __forceinline__ void ldm_x2(uint32_t &r0, uint32_t &r1, uint32_t addr) {
    asm volatile("ldmatrix.sync.aligned.m8n8.x2.shared.b16 {%0,%1}, [%2];\n"
                 : "=r"(r0),"=r"(r1) : "r"(addr));
}
__device__ __forceinline__ void mma16816(float* d, const uint32_t* a, const uint32_t* b) {
    asm volatile("mma.sync.aligned.m16n8k16.row.col.f32.f16.f16.f32 "
                 "{%0,%1,%2,%3}, {%4,%5,%6,%7}, {%8,%9}, {%0,%1,%2,%3};\n"
                 : "+f"(d[0]),"+f"(d[1]),"+f"(d[2]),"+f"(d[3])
                 : "r"(a[0]),"r"(a[1]),"r"(a[2]),"r"(a[3]),"r"(b[0]),"r"(b[1]));
}

__device__ __forceinline__ void load_stage(uint32_t sb, const __half* Ab, const __half* Bb,
                                           int rs, int bm0, int bn0, int kt, int slot, int tid) {
    uint32_t aS = sb + (uint32_t)slot * STB;
    uint32_t bS = aS + A_BYTES;
    int ch = tid & 7, r0 = tid >> 3;
    const __half* ap = Ab + (size_t)bm0 * rs + kt * BK + ch * 8;
    const __half* bp = Bb + (size_t)bn0 * rs + kt * BK + ch * 8;
    #pragma unroll
    for (int r = r0; r < BM; r += 32)
        cp16(aS + (r * 8 + (ch ^ (r & 7))) * 16, ap + (size_t)r * rs);
    #pragma unroll
    for (int r = r0; r < BN; r += 32)
        cp16(bS + (r * 8 + (ch ^ (r & 7))) * 16, bp + (size_t)r * rs);
}

// Flat CTA decode: [0,128) L0 (2n x 8m x 8sp), [128,256) L1 (4n x 8m x 4sp),
//                  [256,320) L2 (8n x 8m), [320,448) L3 (16n x 8m)
__global__ __launch_bounds__(256, 2) void k_gemm(float* __restrict__ out) {
    extern __shared__ __align__(1024) char smem_raw[];
    uint32_t sb = ((uint32_t)__cvta_generic_to_shared(smem_raw) + 1023) & ~1023u;
    const int tid = threadIdx.x, warp = tid >> 5, lane = tid & 31;
    const int wm = (warp >> 2) * 32;      // 2 M-warps
    const int wn = (warp & 3) * 24;       // 4 N-warps, warp tile 32x24

    int bx = blockIdx.x;
    int level, nt, mt, sp;
    if (bx < 128)      { level = 0; sp = bx & 7; int r = bx >> 3; nt = r & 1; mt = r >> 1; }
    else if (bx < 256) { level = 1; int l2 = bx - 128; sp = l2 & 3; int r = l2 >> 2; nt = r & 3; mt = r >> 2; }
    else if (bx < 320) { level = 2; int l2 = bx - 256; sp = 0; nt = l2 & 7;  mt = l2 >> 3; }
    else               { level = 3; int l2 = bx - 320; sp = 0; nt = l2 & 15; mt = l2 >> 4; }

    const __half *Ab, *Bb; int rs, noff, cs, ce;
    if (level == 0) {
        Ab = g_A0; Bb = g_F0; rs = 9216; noff = 0;
        int lo = g_ktlo[mt], nk0 = g_kthi[mt] - lo + 1;
        cs = lo + (nk0 * sp) / 8; ce = lo + (nk0 * (sp + 1)) / 8;
    } else if (level == 1) {
        Ab = g_A1; Bb = g_F1; rs = 2304; noff = 192; cs = 9 * sp; ce = 9 * sp + 9;
    } else if (level == 2) {
        Ab = g_A2; Bb = g_F2; rs = 576;  noff = 576; cs = 0; ce = 9;
    } else {
        Ab = g_A3; Bb = g_F3; rs = 192;  noff = 1344; cs = 0; ce = 3;
    }
    const int nk = ce - cs;
    if (nk <= 0) return;
    const int bm0 = mt * BM, bn0 = nt * BN;

    float acc[2][3][4];
    #pragma unroll
    for (int i = 0; i < 2; i++)
        #pragma unroll
        for (int j = 0; j < 3; j++)
            #pragma unroll
            for (int c = 0; c < 4; c++) acc[i][j][c] = 0.f;

    #pragma unroll
    for (int i = 0; i < 3; i++) {
        if (i < nk) {
            load_stage(sb, Ab, Bb, rs, bm0, bn0, cs + i, i, tid);
            asm volatile("cp.async.commit_group;" ::: "memory");
        }
    }

    for (int j = 0; j < nk; j++) {
        if (j <= nk - 3)      asm volatile("cp.async.wait_group 2;" ::: "memory");
        else if (j == nk - 2) asm volatile("cp.async.wait_group 1;" ::: "memory");
        else                  asm volatile("cp.async.wait_group 0;" ::: "memory");
        __syncthreads();
        if (j + 3 < nk) {
            load_stage(sb, Ab, Bb, rs, bm0, bn0, cs + j + 3, (j + 3) & 3, tid);
            asm volatile("cp.async.commit_group;" ::: "memory");
        }

        const uint32_t aS = sb + (uint32_t)(j & 3) * STB;
        const uint32_t bS = aS + A_BYTES;
        #pragma unroll
        for (int ks = 0; ks < 4; ks++) {
            uint32_t a[2][4];
            #pragma unroll
            for (int mf = 0; mf < 2; mf++) {
                int m  = wm + mf * 16 + (lane & 15);
                int kc = ks * 2 + (lane >> 4);
                ldm_x4(a[mf][0], a[mf][1], a[mf][2], a[mf][3],
                       aS + (m * 8 + (kc ^ (m & 7))) * 16);
            }
            uint32_t b[3][2];
            {
                int g = lane >> 3;
                int n  = wn + (g >> 1) * 8 + (lane & 7);
                int kc = ks * 2 + (g & 1);
                ldm_x4(b[0][0], b[0][1], b[1][0], b[1][1],
                       bS + (n * 8 + (kc ^ (n & 7))) * 16);
            }
            {
                int g = lane >> 3;
                int n  = wn + 16 + (lane & 7);
                int kc = ks * 2 + (g & 1);
                ldm_x2(b[2][0], b[2][1], bS + (n * 8 + (kc ^ (n & 7))) * 16);
            }
            #pragma unroll
            for (int mf = 0; mf < 2; mf++)
                #pragma unroll
                for (int nf = 0; nf < 3; nf++)
                    mma16816(acc[mf][nf], a[mf], b[nf]);
        }
    }

    // Epilogue: scatter rows through perm; split-K levels accumulate atomically.
    int r0 = lane >> 2, c0 = (lane & 3) * 2;
    #pragma unroll
    for (int mf = 0; mf < 2; mf++) {
        int mA = bm0 + wm + mf * 16 + r0;
        int rowA = g_perm[mA];
        int rowB = g_perm[mA + 8];
        #pragma unroll
        for (int nf = 0; nf < 3; nf++) {
            int n = noff + bn0 + wn + nf * 8 + c0;
            float* p0 = &out[(size_t)rowA * CTOT + n];
            float* p1 = &out[(size_t)rowB * CTOT + n];
            if (level <= 1) {
                atomicAdd(p0,     acc[mf][nf][0]);
                atomicAdd(p0 + 1, acc[mf][nf][1]);
                atomicAdd(p1,     acc[mf][nf][2]);
                atomicAdd(p1 + 1, acc[mf][nf][3]);
            } else {
                *(float2*)p0 = make_float2(acc[mf][nf][0], acc[mf][nf][1]);
                *(float2*)p1 = make_float2(acc[mf][nf][2], acc[mf][nf][3]);
            }
        }
    }
}

extern "C" void kernel_launch(void* const* d_in, const int* in_sizes, int n_in,
                              void* d_out, int out_size) {
    const float* feat0 = (const float*)d_in[0];
    const float* feat1 = (const float*)d_in[1];
    const float* feat2 = (const float*)d_in[2];
    const float* feat3 = (const float*)d_in[3];
    const float* boxes = (const float*)d_in[4];
    float* out = (float*)d_out;

    cudaFuncSetAttribute(k_gemm, cudaFuncAttributeMaxDynamicSharedMemorySize, SMEM_SZ);

    k_prep<<<487, 256>>>((const float4*)feat0, (const float4*)feat1,
                         (const float4*)feat2, feat3, boxes, (float4*)out);
    k_weights<<<NBOX, 128>>>(boxes);
    k_gemm<<<448, 256, SMEM_SZ>>>(out);
}